// round 12
// baseline (speedup 1.0000x reference)
#include <cuda_runtime.h>

#define NN   50000
#define NE   800000
#define FIN  16
#define HIDC 32
#define NH   4
#define HC   128
#define NCLS 5
#define EF   8

// ---------------- scratch (static device allocation; no cudaMalloc) ----------
__device__ int   g_is64 = 1;          // probe only ever writes 0 -> deterministic
__device__ int   g_deg[NN];
__device__ int   g_cursor[NN];
__device__ int   g_row[NN + 1];
__device__ int   g_srce[NE];
__device__ int   g_dste[NE];
__device__ int   g_srcs[NE];          // src ids sorted by dst
__device__ float g_ae1[NE * 4];       // per-edge attention logit term, layer 1 (sorted)
__device__ float g_ae2[NE * 4];       // layer 2 (sorted)
__device__ float g_asrc[NN * 4];
__device__ float g_adst[NN * 4];
__device__ float g_buf1[NN * HC];
__device__ float g_buf2[NN * HC];

#define SCB 256
#define NSB ((NN + SCB - 1) / SCB)    // 196
__device__ int g_bsum[NSB];

__device__ __forceinline__ float elu1(float v) {
    return v > 0.f ? v : (__expf(v) - 1.f);
}

typedef unsigned long long ull;
__device__ __forceinline__ ull ffma2(ull a, ull b, ull c) {
    ull d;
    asm("fma.rn.f32x2 %0, %1, %2, %3;" : "=l"(d) : "l"(a), "l"(b), "l"(c));
    return d;
}

// ---------------- prologue: zero degree hist + dtype probe (merged) ----------
__global__ void k_prep(const unsigned* __restrict__ ei_words) {
    int i = blockIdx.x * blockDim.x + threadIdx.x;
    if (i < NN) g_deg[i] = 0;
    if (i < 2048) {
        if (ei_words[2 * i + 1] != 0u) g_is64 = 0;
    }
}

__global__ void k_convert_hist(const void* __restrict__ ei) {
    int e = blockIdx.x * blockDim.x + threadIdx.x;
    if (e >= NE) return;
    int s, d;
    if (g_is64) {
        const long long* p = (const long long*)ei;
        s = (int)p[e]; d = (int)p[NE + e];
    } else {
        const int* p = (const int*)ei;
        s = p[e]; d = p[NE + e];
    }
    g_srce[e] = s; g_dste[e] = d;
    atomicAdd(&g_deg[d], 1);
}

// ---------------- scan stage 1: per-block sums ----------------
__global__ void k_scan1() {
    __shared__ int red[8];
    int t = threadIdx.x, lane = t & 31, wid = t >> 5;
    int i = blockIdx.x * SCB + t;
    int v = (i < NN) ? g_deg[i] : 0;
    #pragma unroll
    for (int off = 16; off; off >>= 1) v += __shfl_xor_sync(0xffffffffu, v, off);
    if (lane == 0) red[wid] = v;
    __syncthreads();
    if (t == 0) {
        int s = 0;
        #pragma unroll
        for (int j = 0; j < 8; j++) s += red[j];
        g_bsum[blockIdx.x] = s;
    }
}

// ---------------- scan stage 2+3 fused ----------------
__global__ void k_scan23() {
    __shared__ int sb[256];
    __shared__ int ws[8];
    int t = threadIdx.x, lane = t & 31, wid = t >> 5;
    sb[t] = (t < NSB) ? g_bsum[t] : 0;
    __syncthreads();
    #pragma unroll
    for (int off = 1; off < 256; off <<= 1) {
        int v = sb[t];
        int u = (t >= off) ? sb[t - off] : 0;
        __syncthreads();
        sb[t] = v + u;
        __syncthreads();
    }
    int blockoff = (blockIdx.x == 0) ? 0 : sb[blockIdx.x - 1];
    int i = blockIdx.x * SCB + t;
    int v = (i < NN) ? g_deg[i] : 0;
    int incl = v;
    #pragma unroll
    for (int off = 1; off < 32; off <<= 1) {
        int u = __shfl_up_sync(0xffffffffu, incl, off);
        if (lane >= off) incl += u;
    }
    if (lane == 31) ws[wid] = incl;
    __syncthreads();
    if (wid == 0) {
        int x = (lane < 8) ? ws[lane] : 0;
        #pragma unroll
        for (int off = 1; off < 8; off <<= 1) {
            int u = __shfl_up_sync(0xffffffffu, x, off);
            if (lane >= off) x += u;
        }
        if (lane < 8) ws[lane] = x;
    }
    __syncthreads();
    int offset = (wid ? ws[wid - 1] : 0) + blockoff;
    int excl = incl - v + offset;
    if (i < NN) { g_row[i] = excl; g_cursor[i] = excl; }
    if (i == 0) g_row[NN] = NE;
}

// ---------------- edge encoder MLP + a_e fold, dst-sorted scatter -----------
// MLP shared loads vectorized: 2x LDS.128 (w1) + 1x LDS.128 (w2 transposed).
__global__ void k_edge_encode(const float* __restrict__ eattr,
                              const float* __restrict__ w1, const float* __restrict__ b1,
                              const float* __restrict__ w2, const float* __restrict__ b2,
                              const float* __restrict__ We1, const float* __restrict__ aew1,
                              const float* __restrict__ We2, const float* __restrict__ aew2) {
    __shared__ float sw1[HIDC * EF];
    __shared__ float sb1[HIDC];
    __shared__ float sw2t[HIDC * NH];   // sw2t[j*4+c] = w2[c*HIDC+j]
    __shared__ float sb2[NH];
    __shared__ float sv[32];
    int t = threadIdx.x;
    if (t < HIDC * EF) sw1[t] = w1[t];
    if (t < HIDC)      sb1[t] = b1[t];
    if (t < HIDC * NH) { int j = t >> 2, c = t & 3; sw2t[t] = w2[c * HIDC + j]; }
    if (t < NH)        sb2[t] = b2[t];
    if (t < 32) {
        const float* We = (t < 16) ? We1 : We2;
        const float* aw = (t < 16) ? aew1 : aew2;
        int idx = t & 15, h = idx >> 2, k = idx & 3;
        float s = 0.f;
        for (int c = 0; c < HIDC; c++)
            s = fmaf(We[(h * HIDC + c) * NH + k], aw[h * HIDC + c], s);
        sv[t] = s;
    }
    __syncthreads();
    int e = blockIdx.x * blockDim.x + t;
    if (e >= NE) return;
    const float4* ea4 = (const float4*)(eattr + e * EF);
    float4 p0 = ea4[0], p1 = ea4[1];
    float o0 = sb2[0], o1 = sb2[1], o2 = sb2[2], o3 = sb2[3];
    #pragma unroll
    for (int j = 0; j < HIDC; j++) {
        float4 wa = *(const float4*)&sw1[j * EF];
        float4 wb = *(const float4*)&sw1[j * EF + 4];
        float h = sb1[j];
        h = fmaf(p0.x, wa.x, h); h = fmaf(p0.y, wa.y, h);
        h = fmaf(p0.z, wa.z, h); h = fmaf(p0.w, wa.w, h);
        h = fmaf(p1.x, wb.x, h); h = fmaf(p1.y, wb.y, h);
        h = fmaf(p1.z, wb.z, h); h = fmaf(p1.w, wb.w, h);
        h = fmaxf(h, 0.f);
        float4 w2v = *(const float4*)&sw2t[j * 4];
        o0 = fmaf(h, w2v.x, o0);
        o1 = fmaf(h, w2v.y, o1);
        o2 = fmaf(h, w2v.z, o2);
        o3 = fmaf(h, w2v.w, o3);
    }
    int src = g_srce[e];
    int dst = g_dste[e];
    int pos = atomicAdd(&g_cursor[dst], 1);
    g_srcs[pos] = src;
    float4 r1, r2;
    r1.x = o0 * sv[0]  + o1 * sv[1]  + o2 * sv[2]  + o3 * sv[3];
    r1.y = o0 * sv[4]  + o1 * sv[5]  + o2 * sv[6]  + o3 * sv[7];
    r1.z = o0 * sv[8]  + o1 * sv[9]  + o2 * sv[10] + o3 * sv[11];
    r1.w = o0 * sv[12] + o1 * sv[13] + o2 * sv[14] + o3 * sv[15];
    r2.x = o0 * sv[16] + o1 * sv[17] + o2 * sv[18] + o3 * sv[19];
    r2.y = o0 * sv[20] + o1 * sv[21] + o2 * sv[22] + o3 * sv[23];
    r2.z = o0 * sv[24] + o1 * sv[25] + o2 * sv[26] + o3 * sv[27];
    r2.w = o0 * sv[28] + o1 * sv[29] + o2 * sv[30] + o3 * sv[31];
    ((float4*)g_ae1)[pos] = r1;
    ((float4*)g_ae2)[pos] = r2;
}

// ---------------- xp = x @ W.T (FIN=16), warp = node, lane = 4 channels -----
#define TS_BLOCKS 1250
#define TS_ITERS  (NN / (TS_BLOCKS * 8))   // 5
__global__ __launch_bounds__(256) void k_transform_small(
        const float* __restrict__ xin, const float* __restrict__ W,
        const float* __restrict__ as_w, const float* __restrict__ ad_w,
        float* __restrict__ out) {
    __shared__ float Ws[FIN * HC];      // Ws[k*128 + c] = W[c*16 + k]
    __shared__ float sas[HC], sad[HC];
    int t = threadIdx.x;   // 256
    for (int i = t; i < HC * FIN; i += 256) {
        int k = i >> 7, c = i & 127;
        Ws[i] = W[c * FIN + k];
    }
    if (t < HC) { sas[t] = as_w[t]; sad[t] = ad_w[t]; }
    __syncthreads();
    int wib = t >> 5, lane = t & 31;
    const float4* Ws4 = (const float4*)Ws;
    float4 sa4 = ((const float4*)sas)[lane];
    float4 sd4 = ((const float4*)sad)[lane];
    #pragma unroll
    for (int g = 0; g < TS_ITERS; g++) {
        int n = (g * TS_BLOCKS + blockIdx.x) * 8 + wib;
        const float4* xr = (const float4*)(xin + n * FIN);
        float4 x0 = xr[0], x1 = xr[1], x2 = xr[2], x3 = xr[3];  // broadcast
        float xk[16] = {x0.x, x0.y, x0.z, x0.w, x1.x, x1.y, x1.z, x1.w,
                        x2.x, x2.y, x2.z, x2.w, x3.x, x3.y, x3.z, x3.w};
        float4 acc = make_float4(0.f, 0.f, 0.f, 0.f);
        #pragma unroll
        for (int k = 0; k < FIN; k++) {
            float4 wv = Ws4[k * 32 + lane];
            acc.x = fmaf(xk[k], wv.x, acc.x);
            acc.y = fmaf(xk[k], wv.y, acc.y);
            acc.z = fmaf(xk[k], wv.z, acc.z);
            acc.w = fmaf(xk[k], wv.w, acc.w);
        }
        ((float4*)(out + n * HC))[lane] = acc;
        float ps = acc.x * sa4.x + acc.y * sa4.y + acc.z * sa4.z + acc.w * sa4.w;
        float pd = acc.x * sd4.x + acc.y * sd4.y + acc.z * sd4.z + acc.w * sd4.w;
        #pragma unroll
        for (int off = 1; off < 8; off <<= 1) {
            ps += __shfl_xor_sync(0xffffffffu, ps, off);
            pd += __shfl_xor_sync(0xffffffffu, pd, off);
        }
        if ((lane & 7) == 0) {
            int h = lane >> 3;
            g_asrc[n * 4 + h] = ps;
            g_adst[n * 4 + h] = pd;
        }
    }
}

// ---------------- xp = h @ W.T (128->128), conflict-free (R10) --------------
#define TMB   128
#define XPAD  132
#define SMEM_BIG ((HC * HC + TMB * XPAD + 2 * HC + 2 * 16 * HC) * 4)
__global__ __launch_bounds__(512, 1) void k_transform_big(
        const float* __restrict__ hin, const float* __restrict__ W,
        const float* __restrict__ as_w, const float* __restrict__ ad_w,
        float* __restrict__ out) {
    extern __shared__ float smem[];
    float* Wt  = smem;                     // [c][k] native, 64 KB
    float* xs  = smem + HC * HC;           // [nl][XPAD]
    float* sas = xs + TMB * XPAD;
    float* sad = sas + HC;
    float* sps = sad + HC;                 // [16][128] a_src partials
    float* spd = sps + 16 * HC;            // [16][128] a_dst partials
    int t = threadIdx.x;
    int n0 = blockIdx.x * TMB;
    for (int i = t; i < HC * HC; i += 512) Wt[i] = W[i];       // pure copy
    for (int i = t; i < TMB * HC; i += 512) {
        int nl = i >> 7, k = i & 127, n = n0 + nl;
        xs[nl * XPAD + k] = (n < NN) ? hin[n * HC + k] : 0.f;
    }
    if (t < HC) { sas[t] = as_w[t]; sad[t] = ad_w[t]; }
    __syncthreads();
    int lane = t & 31, w = t >> 5;
    int ng = w & 1;
    int nd0 = ng * 32 + lane, nd1 = (ng + 2) * 32 + lane;
    const float* xr0 = xs + nd0 * XPAD;
    const float* xr1 = xs + nd1 * XPAD;
    int gn0 = n0 + nd0, gn1 = n0 + nd1;
    #pragma unroll 1
    for (int tile = 0; tile < 2; tile++) {
        int cg = (w >> 1) + 8 * tile;
        const float* wbase = Wt + cg * 8 * HC;
        ull acc0[8], acc1[8];
        #pragma unroll
        for (int j = 0; j < 8; j++) { acc0[j] = 0ull; acc1[j] = 0ull; }
        #pragma unroll 4
        for (int k = 0; k < HC; k += 4) {
            ulonglong2 xv0 = *(const ulonglong2*)(xr0 + k);
            ulonglong2 xv1 = *(const ulonglong2*)(xr1 + k);
            #pragma unroll
            for (int j = 0; j < 8; j++) {
                ulonglong2 wv = *(const ulonglong2*)(wbase + j * HC + k);
                acc0[j] = ffma2(xv0.x, wv.x, acc0[j]);
                acc0[j] = ffma2(xv0.y, wv.y, acc0[j]);
                acc1[j] = ffma2(xv1.x, wv.x, acc1[j]);
                acc1[j] = ffma2(xv1.y, wv.y, acc1[j]);
            }
        }
        float a0[8], a1[8];
        #pragma unroll
        for (int j = 0; j < 8; j++) {
            float2 f0 = *(float2*)&acc0[j];
            float2 f1 = *(float2*)&acc1[j];
            a0[j] = f0.x + f0.y;
            a1[j] = f1.x + f1.y;
        }
        if (gn0 < NN) {
            float4* o4 = (float4*)(out + gn0 * HC + cg * 8);
            o4[0] = make_float4(a0[0], a0[1], a0[2], a0[3]);
            o4[1] = make_float4(a0[4], a0[5], a0[6], a0[7]);
        }
        if (gn1 < NN) {
            float4* o4 = (float4*)(out + gn1 * HC + cg * 8);
            o4[0] = make_float4(a1[0], a1[1], a1[2], a1[3]);
            o4[1] = make_float4(a1[4], a1[5], a1[6], a1[7]);
        }
        float ps0 = 0.f, pd0 = 0.f, ps1 = 0.f, pd1 = 0.f;
        #pragma unroll
        for (int j = 0; j < 8; j++) {
            float sa = sas[cg * 8 + j], sd = sad[cg * 8 + j];
            ps0 = fmaf(a0[j], sa, ps0);  pd0 = fmaf(a0[j], sd, pd0);
            ps1 = fmaf(a1[j], sa, ps1);  pd1 = fmaf(a1[j], sd, pd1);
        }
        sps[cg * HC + nd0] = ps0;  spd[cg * HC + nd0] = pd0;
        sps[cg * HC + nd1] = ps1;  spd[cg * HC + nd1] = pd1;
    }
    __syncthreads();
    {
        int node = t & 127, h = t >> 7;
        int n = n0 + node;
        float ps = 0.f, pd = 0.f;
        #pragma unroll
        for (int j = 0; j < 4; j++) {
            ps += sps[(h * 4 + j) * HC + node];
            pd += spd[(h * 4 + j) * HC + node];
        }
        if (n < NN) { g_asrc[n * 4 + h] = ps; g_adst[n * 4 + h] = pd; }
    }
}

// ---------------- gat batch body (shared by both gat kernels) ---------------
// Accumulates over edges [r0, r1) for head h, lane channels [4l,4l+4).
__device__ __forceinline__ void gat_accum(const float* __restrict__ xp,
                                          const float* __restrict__ ae,
                                          int r0, int r1, int lane, int h,
                                          float ad_h,
                                          float& ax, float& ay, float& az, float& aw,
                                          float& wsum) {
    for (int base = r0; base < r1; base += 8) {
        int m = r1 - base;
        int s[8];
        #pragma unroll
        for (int j = 0; j < 8; j++) {
            int jc = (j < m) ? j : 0;
            s[j] = __ldg(&g_srcs[base + jc]);
        }
        float as[8], av[8];
        float4 xv[8];
        #pragma unroll
        for (int j = 0; j < 8; j++) {
            int jc = (j < m) ? j : 0;
            as[j] = __ldg(&g_asrc[s[j] * 4 + h]);
            av[j] = __ldg(&ae[(base + jc) * 4 + h]);
            xv[j] = __ldg(&((const float4*)(xp + s[j] * HC))[lane]);
        }
        #pragma unroll
        for (int j = 0; j < 8; j++) {
            float l = as[j] + ad_h + av[j];
            l = fmaxf(l, 0.2f * l);
            float w = (j < m) ? __expf(l) : 0.f;
            ax = fmaf(w, xv[j].x, ax);
            ay = fmaf(w, xv[j].y, ay);
            az = fmaf(w, xv[j].z, az);
            aw = fmaf(w, xv[j].w, aw);
            wsum += w;
        }
    }
}

// ---------------- layer-1 gat: 2 warps per node -----------------------------
__global__ __launch_bounds__(256) void k_gat(const float* __restrict__ xp,
                                             const float* __restrict__ ae,
                                             const float* __restrict__ bias,
                                             float* __restrict__ out) {
    __shared__ float4 sacc[4 * 32];
    __shared__ float  swsm[4 * 32];
    int t = threadIdx.x, lane = t & 31, w = t >> 5;
    int nl = w >> 1, half = w & 1;
    int n = blockIdx.x * 4 + nl;           // grid = NN/4 exact
    int row = __ldg(&g_row[n]), end = __ldg(&g_row[n + 1]);
    int cnt = end - row, mid = row + ((cnt + 1) >> 1);
    int r0 = half ? mid : row, r1 = half ? end : mid;
    int h = lane >> 3;
    float ad_h = __ldg(&g_adst[n * 4 + h]);
    float ax = 0.f, ay = 0.f, az = 0.f, aw = 0.f, wsum = 0.f;
    gat_accum(xp, ae, r0, r1, lane, h, ad_h, ax, ay, az, aw, wsum);
    if (half) {
        sacc[nl * 32 + lane] = make_float4(ax, ay, az, aw);
        swsm[nl * 32 + lane] = wsum;
    }
    __syncthreads();
    if (!half) {
        float4 b = sacc[nl * 32 + lane];
        ax += b.x; ay += b.y; az += b.z; aw += b.w;
        wsum += swsm[nl * 32 + lane];
        float inv = 1.f / (wsum + 1e-16f);
        float4 b4 = __ldg(&((const float4*)bias)[lane]);
        float4 o;
        o.x = elu1(ax * inv + b4.x);
        o.y = elu1(ay * inv + b4.y);
        o.z = elu1(az * inv + b4.z);
        o.w = elu1(aw * inv + b4.w);
        ((float4*)(out + n * HC))[lane] = o;
    }
}

// ---------------- layer-2 gat + fused skip/classifier: 2 warps per node -----
__global__ __launch_bounds__(256) void k_gat2_final(
        const float* __restrict__ xp, const float* __restrict__ ae,
        const float* __restrict__ bias,
        const float* __restrict__ x,
        const float* __restrict__ skip_w, const float* __restrict__ skip_b,
        const float* __restrict__ cls_w, const float* __restrict__ cls_b,
        float* __restrict__ out) {
    __shared__ float swT[FIN * HC];     // swT[k*128+c] = skip_w[c*16+k]
    __shared__ float scw[NCLS * HC];
    __shared__ float4 sacc[4 * 32];
    __shared__ float  swsm[4 * 32];
    int t = threadIdx.x;   // 256, grid = NN/4 exact
    for (int i = t; i < FIN * HC; i += 256) {
        int k = i >> 7, c = i & 127;
        swT[i] = skip_w[c * FIN + k];
    }
    for (int i = t; i < NCLS * HC; i += 256) scw[i] = cls_w[i];
    __syncthreads();
    int lane = t & 31, w = t >> 5;
    int nl = w >> 1, half = w & 1;
    int n = blockIdx.x * 4 + nl;
    int row = __ldg(&g_row[n]), end = __ldg(&g_row[n + 1]);
    int cnt = end - row, mid = row + ((cnt + 1) >> 1);
    int r0 = half ? mid : row, r1 = half ? end : mid;
    int h = lane >> 3;
    float ad_h = __ldg(&g_adst[n * 4 + h]);
    float ax = 0.f, ay = 0.f, az = 0.f, aw = 0.f, wsum = 0.f;
    gat_accum(xp, ae, r0, r1, lane, h, ad_h, ax, ay, az, aw, wsum);
    if (half) {
        sacc[nl * 32 + lane] = make_float4(ax, ay, az, aw);
        swsm[nl * 32 + lane] = wsum;
    }
    __syncthreads();
    if (!half) {
        float4 b = sacc[nl * 32 + lane];
        ax += b.x; ay += b.y; az += b.z; aw += b.w;
        wsum += swsm[nl * 32 + lane];
        float inv = 1.f / (wsum + 1e-16f);
        float4 b4 = __ldg(&((const float4*)bias)[lane]);
        float4 hv;
        hv.x = elu1(ax * inv + b4.x);
        hv.y = elu1(ay * inv + b4.y);
        hv.z = elu1(az * inv + b4.z);
        hv.w = elu1(aw * inv + b4.w);
        // ---- fused skip + classifier (same arithmetic as old k_final) ----
        const float4* xr = (const float4*)(x + n * FIN);
        float4 x0 = xr[0], x1 = xr[1], x2 = xr[2], x3 = xr[3];
        float xk[16] = {x0.x, x0.y, x0.z, x0.w, x1.x, x1.y, x1.z, x1.w,
                        x2.x, x2.y, x2.z, x2.w, x3.x, x3.y, x3.z, x3.w};
        const float4* swT4 = (const float4*)swT;
        const float4* scw4 = (const float4*)scw;
        float4 sk = ((const float4*)skip_b)[lane];
        #pragma unroll
        for (int k = 0; k < FIN; k++) {
            float4 wv = swT4[k * 32 + lane];
            sk.x = fmaf(xk[k], wv.x, sk.x);
            sk.y = fmaf(xk[k], wv.y, sk.y);
            sk.z = fmaf(xk[k], wv.z, sk.z);
            sk.w = fmaf(xk[k], wv.w, sk.w);
        }
        float4 v = make_float4(hv.x + sk.x, hv.y + sk.y, hv.z + sk.z, hv.w + sk.w);
        float p[NCLS];
        #pragma unroll
        for (int c = 0; c < NCLS; c++) {
            float4 cw = scw4[c * 32 + lane];
            p[c] = v.x * cw.x + v.y * cw.y + v.z * cw.z + v.w * cw.w;
            #pragma unroll
            for (int off = 16; off; off >>= 1)
                p[c] += __shfl_xor_sync(0xffffffffu, p[c], off);
        }
        if (lane < NCLS) out[n * NCLS + lane] = p[lane] + cls_b[lane];
    }
}

extern "C" void kernel_launch(void* const* d_in, const int* in_sizes, int n_in,
                              void* d_out, int out_size) {
    const float* x      = (const float*)d_in[0];
    const void*  ei     = d_in[1];
    const float* eattr  = (const float*)d_in[2];
    const float* ee_w1  = (const float*)d_in[3];
    const float* ee_b1  = (const float*)d_in[4];
    const float* ee_w2  = (const float*)d_in[5];
    const float* ee_b2  = (const float*)d_in[6];
    const float* g1_W   = (const float*)d_in[7];
    const float* g1_We  = (const float*)d_in[8];
    const float* g1_as  = (const float*)d_in[9];
    const float* g1_ad  = (const float*)d_in[10];
    const float* g1_ae  = (const float*)d_in[11];
    const float* g1_b   = (const float*)d_in[12];
    const float* g2_W   = (const float*)d_in[13];
    const float* g2_We  = (const float*)d_in[14];
    const float* g2_as  = (const float*)d_in[15];
    const float* g2_ad  = (const float*)d_in[16];
    const float* g2_ae  = (const float*)d_in[17];
    const float* g2_b   = (const float*)d_in[18];
    const float* skip_w = (const float*)d_in[19];
    const float* skip_b = (const float*)d_in[20];
    const float* cls_w  = (const float*)d_in[21];
    const float* cls_b  = (const float*)d_in[22];
    float* out = (float*)d_out;

    static_assert(SMEM_BIG <= 227 * 1024, "smem");
    cudaFuncSetAttribute(k_transform_big, cudaFuncAttributeMaxDynamicSharedMemorySize, SMEM_BIG);

    float *buf1, *buf2;
    cudaGetSymbolAddress((void**)&buf1, g_buf1);
    cudaGetSymbolAddress((void**)&buf2, g_buf2);

    // launches (tsmall 4th: ncu's fixed capture slot)
    k_prep<<<NSB, SCB>>>((const unsigned*)ei);                          // 1
    k_convert_hist<<<NE / 256, 256>>>(ei);                              // 2
    k_scan1<<<NSB, SCB>>>();                                            // 3
    k_transform_small<<<TS_BLOCKS, 256>>>(x, g1_W, g1_as, g1_ad, buf1); // 4
    k_scan23<<<NSB, SCB>>>();                                           // 5
    k_edge_encode<<<NE / 256, 256>>>(eattr, ee_w1, ee_b1, ee_w2, ee_b2,
                                     g1_We, g1_ae, g2_We, g2_ae);       // 6
    // --- layer 1 (2 warps/node) ---
    k_gat<<<NN / 4, 256>>>(buf1, g_ae1, g1_b, buf2);                    // 7
    // --- layer 2 (gat fused with skip + classifier, 2 warps/node) ---
    k_transform_big<<<(NN + TMB - 1) / TMB, 512, SMEM_BIG>>>(buf2, g2_W, g2_as, g2_ad, buf1); // 8
    k_gat2_final<<<NN / 4, 256>>>(buf1, g_ae2, g2_b,
                                  x, skip_w, skip_b, cls_w, cls_b, out); // 9
}

// round 13
// speedup vs baseline: 1.1263x; 1.1263x over previous
#include <cuda_runtime.h>

#define NN   50000
#define NE   800000
#define FIN  16
#define HIDC 32
#define NH   4
#define HC   128
#define NCLS 5
#define EF   8

// ---------------- scratch (static device allocation; no cudaMalloc) ----------
__device__ int   g_is64 = 1;          // probe only ever writes 0 -> deterministic
__device__ int   g_deg[NN];
__device__ int   g_cursor[NN];
__device__ int   g_row[NN + 1];
__device__ int   g_srce[NE];
__device__ int   g_dste[NE];
__device__ int   g_srcs[NE];          // src ids sorted by dst
__device__ float g_ae1[NE * 4];       // per-edge attention logit term, layer 1 (sorted)
__device__ float g_ae2[NE * 4];       // layer 2 (sorted)
__device__ float g_asrc[NN * 4];
__device__ float g_adst[NN * 4];
__device__ float g_buf1[NN * HC];
__device__ float g_buf2[NN * HC];

#define SCB 256
#define NSB ((NN + SCB - 1) / SCB)    // 196
__device__ int g_bsum[NSB];

__device__ __forceinline__ float elu1(float v) {
    return v > 0.f ? v : (__expf(v) - 1.f);
}

typedef unsigned long long ull;
__device__ __forceinline__ ull ffma2(ull a, ull b, ull c) {
    ull d;
    asm("fma.rn.f32x2 %0, %1, %2, %3;" : "=l"(d) : "l"(a), "l"(b), "l"(c));
    return d;
}

// ---------------- prologue: zero degree hist + dtype probe (merged) ----------
__global__ void k_prep(const unsigned* __restrict__ ei_words) {
    int i = blockIdx.x * blockDim.x + threadIdx.x;
    if (i < NN) g_deg[i] = 0;
    if (i < 2048) {
        if (ei_words[2 * i + 1] != 0u) g_is64 = 0;
    }
}

__global__ void k_convert_hist(const void* __restrict__ ei) {
    int e = blockIdx.x * blockDim.x + threadIdx.x;
    if (e >= NE) return;
    int s, d;
    if (g_is64) {
        const long long* p = (const long long*)ei;
        s = (int)p[e]; d = (int)p[NE + e];
    } else {
        const int* p = (const int*)ei;
        s = p[e]; d = p[NE + e];
    }
    g_srce[e] = s; g_dste[e] = d;
    atomicAdd(&g_deg[d], 1);
}

// ---------------- scan stage 1: per-block sums ----------------
__global__ void k_scan1() {
    __shared__ int red[8];
    int t = threadIdx.x, lane = t & 31, wid = t >> 5;
    int i = blockIdx.x * SCB + t;
    int v = (i < NN) ? g_deg[i] : 0;
    #pragma unroll
    for (int off = 16; off; off >>= 1) v += __shfl_xor_sync(0xffffffffu, v, off);
    if (lane == 0) red[wid] = v;
    __syncthreads();
    if (t == 0) {
        int s = 0;
        #pragma unroll
        for (int j = 0; j < 8; j++) s += red[j];
        g_bsum[blockIdx.x] = s;
    }
}

// ---------------- scan stage 2+3 fused ----------------
__global__ void k_scan23() {
    __shared__ int sb[256];
    __shared__ int ws[8];
    int t = threadIdx.x, lane = t & 31, wid = t >> 5;
    sb[t] = (t < NSB) ? g_bsum[t] : 0;
    __syncthreads();
    #pragma unroll
    for (int off = 1; off < 256; off <<= 1) {
        int v = sb[t];
        int u = (t >= off) ? sb[t - off] : 0;
        __syncthreads();
        sb[t] = v + u;
        __syncthreads();
    }
    int blockoff = (blockIdx.x == 0) ? 0 : sb[blockIdx.x - 1];
    int i = blockIdx.x * SCB + t;
    int v = (i < NN) ? g_deg[i] : 0;
    int incl = v;
    #pragma unroll
    for (int off = 1; off < 32; off <<= 1) {
        int u = __shfl_up_sync(0xffffffffu, incl, off);
        if (lane >= off) incl += u;
    }
    if (lane == 31) ws[wid] = incl;
    __syncthreads();
    if (wid == 0) {
        int x = (lane < 8) ? ws[lane] : 0;
        #pragma unroll
        for (int off = 1; off < 8; off <<= 1) {
            int u = __shfl_up_sync(0xffffffffu, x, off);
            if (lane >= off) x += u;
        }
        if (lane < 8) ws[lane] = x;
    }
    __syncthreads();
    int offset = (wid ? ws[wid - 1] : 0) + blockoff;
    int excl = incl - v + offset;
    if (i < NN) { g_row[i] = excl; g_cursor[i] = excl; }
    if (i == 0) g_row[NN] = NE;
}

// ---------------- edge encoder MLP + a_e fold, dst-sorted scatter -----------
// MLP shared loads vectorized: 2x LDS.128 (w1) + 1x LDS.128 (w2 transposed).
__global__ void k_edge_encode(const float* __restrict__ eattr,
                              const float* __restrict__ w1, const float* __restrict__ b1,
                              const float* __restrict__ w2, const float* __restrict__ b2,
                              const float* __restrict__ We1, const float* __restrict__ aew1,
                              const float* __restrict__ We2, const float* __restrict__ aew2) {
    __shared__ float sw1[HIDC * EF];
    __shared__ float sb1[HIDC];
    __shared__ float sw2t[HIDC * NH];   // sw2t[j*4+c] = w2[c*HIDC+j]
    __shared__ float sb2[NH];
    __shared__ float sv[32];
    int t = threadIdx.x;
    if (t < HIDC * EF) sw1[t] = w1[t];
    if (t < HIDC)      sb1[t] = b1[t];
    if (t < HIDC * NH) { int j = t >> 2, c = t & 3; sw2t[t] = w2[c * HIDC + j]; }
    if (t < NH)        sb2[t] = b2[t];
    if (t < 32) {
        const float* We = (t < 16) ? We1 : We2;
        const float* aw = (t < 16) ? aew1 : aew2;
        int idx = t & 15, h = idx >> 2, k = idx & 3;
        float s = 0.f;
        for (int c = 0; c < HIDC; c++)
            s = fmaf(We[(h * HIDC + c) * NH + k], aw[h * HIDC + c], s);
        sv[t] = s;
    }
    __syncthreads();
    int e = blockIdx.x * blockDim.x + t;
    if (e >= NE) return;
    const float4* ea4 = (const float4*)(eattr + e * EF);
    float4 p0 = ea4[0], p1 = ea4[1];
    float o0 = sb2[0], o1 = sb2[1], o2 = sb2[2], o3 = sb2[3];
    #pragma unroll
    for (int j = 0; j < HIDC; j++) {
        float4 wa = *(const float4*)&sw1[j * EF];
        float4 wb = *(const float4*)&sw1[j * EF + 4];
        float h = sb1[j];
        h = fmaf(p0.x, wa.x, h); h = fmaf(p0.y, wa.y, h);
        h = fmaf(p0.z, wa.z, h); h = fmaf(p0.w, wa.w, h);
        h = fmaf(p1.x, wb.x, h); h = fmaf(p1.y, wb.y, h);
        h = fmaf(p1.z, wb.z, h); h = fmaf(p1.w, wb.w, h);
        h = fmaxf(h, 0.f);
        float4 w2v = *(const float4*)&sw2t[j * 4];
        o0 = fmaf(h, w2v.x, o0);
        o1 = fmaf(h, w2v.y, o1);
        o2 = fmaf(h, w2v.z, o2);
        o3 = fmaf(h, w2v.w, o3);
    }
    int src = g_srce[e];
    int dst = g_dste[e];
    int pos = atomicAdd(&g_cursor[dst], 1);
    g_srcs[pos] = src;
    float4 r1, r2;
    r1.x = o0 * sv[0]  + o1 * sv[1]  + o2 * sv[2]  + o3 * sv[3];
    r1.y = o0 * sv[4]  + o1 * sv[5]  + o2 * sv[6]  + o3 * sv[7];
    r1.z = o0 * sv[8]  + o1 * sv[9]  + o2 * sv[10] + o3 * sv[11];
    r1.w = o0 * sv[12] + o1 * sv[13] + o2 * sv[14] + o3 * sv[15];
    r2.x = o0 * sv[16] + o1 * sv[17] + o2 * sv[18] + o3 * sv[19];
    r2.y = o0 * sv[20] + o1 * sv[21] + o2 * sv[22] + o3 * sv[23];
    r2.z = o0 * sv[24] + o1 * sv[25] + o2 * sv[26] + o3 * sv[27];
    r2.w = o0 * sv[28] + o1 * sv[29] + o2 * sv[30] + o3 * sv[31];
    ((float4*)g_ae1)[pos] = r1;
    ((float4*)g_ae2)[pos] = r2;
}

// ---------------- xp = x @ W.T (FIN=16), warp = node, lane = 4 channels -----
#define TS_BLOCKS 1250
#define TS_ITERS  (NN / (TS_BLOCKS * 8))   // 5
__global__ __launch_bounds__(256) void k_transform_small(
        const float* __restrict__ xin, const float* __restrict__ W,
        const float* __restrict__ as_w, const float* __restrict__ ad_w,
        float* __restrict__ out) {
    __shared__ float Ws[FIN * HC];      // Ws[k*128 + c] = W[c*16 + k]
    __shared__ float sas[HC], sad[HC];
    int t = threadIdx.x;   // 256
    for (int i = t; i < HC * FIN; i += 256) {
        int k = i >> 7, c = i & 127;
        Ws[i] = W[c * FIN + k];
    }
    if (t < HC) { sas[t] = as_w[t]; sad[t] = ad_w[t]; }
    __syncthreads();
    int wib = t >> 5, lane = t & 31;
    const float4* Ws4 = (const float4*)Ws;
    float4 sa4 = ((const float4*)sas)[lane];
    float4 sd4 = ((const float4*)sad)[lane];
    #pragma unroll
    for (int g = 0; g < TS_ITERS; g++) {
        int n = (g * TS_BLOCKS + blockIdx.x) * 8 + wib;
        const float4* xr = (const float4*)(xin + n * FIN);
        float4 x0 = xr[0], x1 = xr[1], x2 = xr[2], x3 = xr[3];  // broadcast
        float xk[16] = {x0.x, x0.y, x0.z, x0.w, x1.x, x1.y, x1.z, x1.w,
                        x2.x, x2.y, x2.z, x2.w, x3.x, x3.y, x3.z, x3.w};
        float4 acc = make_float4(0.f, 0.f, 0.f, 0.f);
        #pragma unroll
        for (int k = 0; k < FIN; k++) {
            float4 wv = Ws4[k * 32 + lane];
            acc.x = fmaf(xk[k], wv.x, acc.x);
            acc.y = fmaf(xk[k], wv.y, acc.y);
            acc.z = fmaf(xk[k], wv.z, acc.z);
            acc.w = fmaf(xk[k], wv.w, acc.w);
        }
        ((float4*)(out + n * HC))[lane] = acc;
        float ps = acc.x * sa4.x + acc.y * sa4.y + acc.z * sa4.z + acc.w * sa4.w;
        float pd = acc.x * sd4.x + acc.y * sd4.y + acc.z * sd4.z + acc.w * sd4.w;
        #pragma unroll
        for (int off = 1; off < 8; off <<= 1) {
            ps += __shfl_xor_sync(0xffffffffu, ps, off);
            pd += __shfl_xor_sync(0xffffffffu, pd, off);
        }
        if ((lane & 7) == 0) {
            int h = lane >> 3;
            g_asrc[n * 4 + h] = ps;
            g_adst[n * 4 + h] = pd;
        }
    }
}

// ---------------- xp = h @ W.T (128->128), conflict-free (R10) --------------
#define TMB   128
#define XPAD  132
#define SMEM_BIG ((HC * HC + TMB * XPAD + 2 * HC + 2 * 16 * HC) * 4)
__global__ __launch_bounds__(512, 1) void k_transform_big(
        const float* __restrict__ hin, const float* __restrict__ W,
        const float* __restrict__ as_w, const float* __restrict__ ad_w,
        float* __restrict__ out) {
    extern __shared__ float smem[];
    float* Wt  = smem;                     // [c][k] native, 64 KB
    float* xs  = smem + HC * HC;           // [nl][XPAD]
    float* sas = xs + TMB * XPAD;
    float* sad = sas + HC;
    float* sps = sad + HC;                 // [16][128] a_src partials
    float* spd = sps + 16 * HC;            // [16][128] a_dst partials
    int t = threadIdx.x;
    int n0 = blockIdx.x * TMB;
    for (int i = t; i < HC * HC; i += 512) Wt[i] = W[i];       // pure copy
    for (int i = t; i < TMB * HC; i += 512) {
        int nl = i >> 7, k = i & 127, n = n0 + nl;
        xs[nl * XPAD + k] = (n < NN) ? hin[n * HC + k] : 0.f;
    }
    if (t < HC) { sas[t] = as_w[t]; sad[t] = ad_w[t]; }
    __syncthreads();
    int lane = t & 31, w = t >> 5;
    int ng = w & 1;
    int nd0 = ng * 32 + lane, nd1 = (ng + 2) * 32 + lane;
    const float* xr0 = xs + nd0 * XPAD;
    const float* xr1 = xs + nd1 * XPAD;
    int gn0 = n0 + nd0, gn1 = n0 + nd1;
    #pragma unroll 1
    for (int tile = 0; tile < 2; tile++) {
        int cg = (w >> 1) + 8 * tile;
        const float* wbase = Wt + cg * 8 * HC;
        ull acc0[8], acc1[8];
        #pragma unroll
        for (int j = 0; j < 8; j++) { acc0[j] = 0ull; acc1[j] = 0ull; }
        #pragma unroll 4
        for (int k = 0; k < HC; k += 4) {
            ulonglong2 xv0 = *(const ulonglong2*)(xr0 + k);
            ulonglong2 xv1 = *(const ulonglong2*)(xr1 + k);
            #pragma unroll
            for (int j = 0; j < 8; j++) {
                ulonglong2 wv = *(const ulonglong2*)(wbase + j * HC + k);
                acc0[j] = ffma2(xv0.x, wv.x, acc0[j]);
                acc0[j] = ffma2(xv0.y, wv.y, acc0[j]);
                acc1[j] = ffma2(xv1.x, wv.x, acc1[j]);
                acc1[j] = ffma2(xv1.y, wv.y, acc1[j]);
            }
        }
        float a0[8], a1[8];
        #pragma unroll
        for (int j = 0; j < 8; j++) {
            float2 f0 = *(float2*)&acc0[j];
            float2 f1 = *(float2*)&acc1[j];
            a0[j] = f0.x + f0.y;
            a1[j] = f1.x + f1.y;
        }
        if (gn0 < NN) {
            float4* o4 = (float4*)(out + gn0 * HC + cg * 8);
            o4[0] = make_float4(a0[0], a0[1], a0[2], a0[3]);
            o4[1] = make_float4(a0[4], a0[5], a0[6], a0[7]);
        }
        if (gn1 < NN) {
            float4* o4 = (float4*)(out + gn1 * HC + cg * 8);
            o4[0] = make_float4(a1[0], a1[1], a1[2], a1[3]);
            o4[1] = make_float4(a1[4], a1[5], a1[6], a1[7]);
        }
        float ps0 = 0.f, pd0 = 0.f, ps1 = 0.f, pd1 = 0.f;
        #pragma unroll
        for (int j = 0; j < 8; j++) {
            float sa = sas[cg * 8 + j], sd = sad[cg * 8 + j];
            ps0 = fmaf(a0[j], sa, ps0);  pd0 = fmaf(a0[j], sd, pd0);
            ps1 = fmaf(a1[j], sa, ps1);  pd1 = fmaf(a1[j], sd, pd1);
        }
        sps[cg * HC + nd0] = ps0;  spd[cg * HC + nd0] = pd0;
        sps[cg * HC + nd1] = ps1;  spd[cg * HC + nd1] = pd1;
    }
    __syncthreads();
    {
        int node = t & 127, h = t >> 7;
        int n = n0 + node;
        float ps = 0.f, pd = 0.f;
        #pragma unroll
        for (int j = 0; j < 4; j++) {
            ps += sps[(h * 4 + j) * HC + node];
            pd += spd[(h * 4 + j) * HC + node];
        }
        if (n < NN) { g_asrc[n * 4 + h] = ps; g_adst[n * 4 + h] = pd; }
    }
}

// ---------------- layer-1 gat: per-dst softmax + aggregation (R7/R11) -------
__global__ void k_gat(const float* __restrict__ xp,
                      const float* __restrict__ ae,
                      const float* __restrict__ bias,
                      float* __restrict__ out) {
    int warp = (blockIdx.x * blockDim.x + threadIdx.x) >> 5;
    int lane = threadIdx.x & 31;
    if (warp >= NN) return;
    int n = warp;
    int row = __ldg(&g_row[n]), end = __ldg(&g_row[n + 1]);
    int h = lane >> 3;
    float ad_h = __ldg(&g_adst[n * 4 + h]);
    float ax = 0.f, ay = 0.f, az = 0.f, aw = 0.f, wsum = 0.f;
    for (int base = row; base < end; base += 8) {
        int m = end - base;
        int s[8];
        #pragma unroll
        for (int j = 0; j < 8; j++) {
            int jc = (j < m) ? j : 0;
            s[j] = __ldg(&g_srcs[base + jc]);
        }
        float as[8], av[8];
        float4 xv[8];
        #pragma unroll
        for (int j = 0; j < 8; j++) {
            int jc = (j < m) ? j : 0;
            as[j] = __ldg(&g_asrc[s[j] * 4 + h]);
            av[j] = __ldg(&ae[(base + jc) * 4 + h]);
            xv[j] = __ldg(&((const float4*)(xp + s[j] * HC))[lane]);
        }
        #pragma unroll
        for (int j = 0; j < 8; j++) {
            float l = as[j] + ad_h + av[j];
            l = fmaxf(l, 0.2f * l);
            float w = (j < m) ? __expf(l) : 0.f;
            ax = fmaf(w, xv[j].x, ax);
            ay = fmaf(w, xv[j].y, ay);
            az = fmaf(w, xv[j].z, az);
            aw = fmaf(w, xv[j].w, aw);
            wsum += w;
        }
    }
    float inv = 1.f / (wsum + 1e-16f);
    float4 b4 = __ldg(&((const float4*)bias)[lane]);
    float4 o;
    o.x = elu1(ax * inv + b4.x);
    o.y = elu1(ay * inv + b4.y);
    o.z = elu1(az * inv + b4.z);
    o.w = elu1(aw * inv + b4.w);
    ((float4*)(out + n * HC))[lane] = o;
}

// ---------------- layer-2 gat + fused skip/classifier (R11) -----------------
__global__ __launch_bounds__(256) void k_gat2_final(
        const float* __restrict__ xp, const float* __restrict__ ae,
        const float* __restrict__ bias,
        const float* __restrict__ x,
        const float* __restrict__ skip_w, const float* __restrict__ skip_b,
        const float* __restrict__ cls_w, const float* __restrict__ cls_b,
        float* __restrict__ out) {
    __shared__ float swT[FIN * HC];     // swT[k*128+c] = skip_w[c*16+k]
    __shared__ float scw[NCLS * HC];
    int t = threadIdx.x;   // 256, grid = NN/8 exactly -> all warps valid
    for (int i = t; i < FIN * HC; i += 256) {
        int k = i >> 7, c = i & 127;
        swT[i] = skip_w[c * FIN + k];
    }
    for (int i = t; i < NCLS * HC; i += 256) scw[i] = cls_w[i];
    __syncthreads();
    int n = blockIdx.x * 8 + (t >> 5);
    int lane = t & 31;
    int row = __ldg(&g_row[n]), end = __ldg(&g_row[n + 1]);
    int h = lane >> 3;
    float ad_h = __ldg(&g_adst[n * 4 + h]);
    float ax = 0.f, ay = 0.f, az = 0.f, aw = 0.f, wsum = 0.f;
    for (int base = row; base < end; base += 8) {
        int m = end - base;
        int s[8];
        #pragma unroll
        for (int j = 0; j < 8; j++) {
            int jc = (j < m) ? j : 0;
            s[j] = __ldg(&g_srcs[base + jc]);
        }
        float as[8], av[8];
        float4 xv[8];
        #pragma unroll
        for (int j = 0; j < 8; j++) {
            int jc = (j < m) ? j : 0;
            as[j] = __ldg(&g_asrc[s[j] * 4 + h]);
            av[j] = __ldg(&ae[(base + jc) * 4 + h]);
            xv[j] = __ldg(&((const float4*)(xp + s[j] * HC))[lane]);
        }
        #pragma unroll
        for (int j = 0; j < 8; j++) {
            float l = as[j] + ad_h + av[j];
            l = fmaxf(l, 0.2f * l);
            float w = (j < m) ? __expf(l) : 0.f;
            ax = fmaf(w, xv[j].x, ax);
            ay = fmaf(w, xv[j].y, ay);
            az = fmaf(w, xv[j].z, az);
            aw = fmaf(w, xv[j].w, aw);
            wsum += w;
        }
    }
    float inv = 1.f / (wsum + 1e-16f);
    float4 b4 = __ldg(&((const float4*)bias)[lane]);
    float4 hv;
    hv.x = elu1(ax * inv + b4.x);
    hv.y = elu1(ay * inv + b4.y);
    hv.z = elu1(az * inv + b4.z);
    hv.w = elu1(aw * inv + b4.w);
    // ---- fused skip + classifier (same arithmetic as old k_final) ----
    const float4* xr = (const float4*)(x + n * FIN);
    float4 x0 = xr[0], x1 = xr[1], x2 = xr[2], x3 = xr[3];
    float xk[16] = {x0.x, x0.y, x0.z, x0.w, x1.x, x1.y, x1.z, x1.w,
                    x2.x, x2.y, x2.z, x2.w, x3.x, x3.y, x3.z, x3.w};
    const float4* swT4 = (const float4*)swT;
    const float4* scw4 = (const float4*)scw;
    float4 sk = ((const float4*)skip_b)[lane];
    #pragma unroll
    for (int k = 0; k < FIN; k++) {
        float4 wv = swT4[k * 32 + lane];
        sk.x = fmaf(xk[k], wv.x, sk.x);
        sk.y = fmaf(xk[k], wv.y, sk.y);
        sk.z = fmaf(xk[k], wv.z, sk.z);
        sk.w = fmaf(xk[k], wv.w, sk.w);
    }
    float4 v = make_float4(hv.x + sk.x, hv.y + sk.y, hv.z + sk.z, hv.w + sk.w);
    float p[NCLS];
    #pragma unroll
    for (int c = 0; c < NCLS; c++) {
        float4 cw = scw4[c * 32 + lane];
        p[c] = v.x * cw.x + v.y * cw.y + v.z * cw.z + v.w * cw.w;
        #pragma unroll
        for (int off = 16; off; off >>= 1)
            p[c] += __shfl_xor_sync(0xffffffffu, p[c], off);
    }
    if (lane < NCLS) out[n * NCLS + lane] = p[lane] + cls_b[lane];
}

extern "C" void kernel_launch(void* const* d_in, const int* in_sizes, int n_in,
                              void* d_out, int out_size) {
    const float* x      = (const float*)d_in[0];
    const void*  ei     = d_in[1];
    const float* eattr  = (const float*)d_in[2];
    const float* ee_w1  = (const float*)d_in[3];
    const float* ee_b1  = (const float*)d_in[4];
    const float* ee_w2  = (const float*)d_in[5];
    const float* ee_b2  = (const float*)d_in[6];
    const float* g1_W   = (const float*)d_in[7];
    const float* g1_We  = (const float*)d_in[8];
    const float* g1_as  = (const float*)d_in[9];
    const float* g1_ad  = (const float*)d_in[10];
    const float* g1_ae  = (const float*)d_in[11];
    const float* g1_b   = (const float*)d_in[12];
    const float* g2_W   = (const float*)d_in[13];
    const float* g2_We  = (const float*)d_in[14];
    const float* g2_as  = (const float*)d_in[15];
    const float* g2_ad  = (const float*)d_in[16];
    const float* g2_ae  = (const float*)d_in[17];
    const float* g2_b   = (const float*)d_in[18];
    const float* skip_w = (const float*)d_in[19];
    const float* skip_b = (const float*)d_in[20];
    const float* cls_w  = (const float*)d_in[21];
    const float* cls_b  = (const float*)d_in[22];
    float* out = (float*)d_out;

    static_assert(SMEM_BIG <= 227 * 1024, "smem");
    cudaFuncSetAttribute(k_transform_big, cudaFuncAttributeMaxDynamicSharedMemorySize, SMEM_BIG);

    float *buf1, *buf2;
    cudaGetSymbolAddress((void**)&buf1, g_buf1);
    cudaGetSymbolAddress((void**)&buf2, g_buf2);

    // launches (tsmall 4th: ncu's fixed capture slot)
    k_prep<<<NSB, SCB>>>((const unsigned*)ei);                          // 1
    k_convert_hist<<<NE / 256, 256>>>(ei);                              // 2
    k_scan1<<<NSB, SCB>>>();                                            // 3
    k_transform_small<<<TS_BLOCKS, 256>>>(x, g1_W, g1_as, g1_ad, buf1); // 4
    k_scan23<<<NSB, SCB>>>();                                           // 5
    k_edge_encode<<<NE / 256, 256>>>(eattr, ee_w1, ee_b1, ee_w2, ee_b2,
                                     g1_We, g1_ae, g2_We, g2_ae);       // 6
    // --- layer 1 ---
    k_gat<<<(NN * 32 + 255) / 256, 256>>>(buf1, g_ae1, g1_b, buf2);     // 7
    // --- layer 2 (gat fused with skip + classifier) ---
    k_transform_big<<<(NN + TMB - 1) / TMB, 512, SMEM_BIG>>>(buf2, g2_W, g2_as, g2_ad, buf1); // 8
    k_gat2_final<<<NN / 8, 256>>>(buf1, g_ae2, g2_b,
                                  x, skip_w, skip_b, cls_w, cls_b, out); // 9
}

// round 14
// speedup vs baseline: 1.3584x; 1.2060x over previous
#include <cuda_runtime.h>

#define NN   50000
#define NE   800000
#define FIN  16
#define HIDC 32
#define NH   4
#define HC   128
#define NCLS 5
#define EF   8

// ---------------- scratch (static device allocation; no cudaMalloc) ----------
__device__ int   g_is64 = 1;          // probe only ever writes 0 -> deterministic
__device__ int   g_deg[NN];
__device__ int   g_cursor[NN];
__device__ int   g_row[NN + 1];
__device__ int   g_srce[NE];
__device__ int   g_dste[NE];
__device__ int   g_srcs[NE];          // src ids sorted by dst
__device__ int   g_dsts[NE];          // dst ids sorted by dst (for layer-2 logits)
__device__ float g_ae1[NE * 4];       // layer-1: final softmax weights w1 (sorted)
__device__ float g_ae2[NE * 4];       // layer-2: ae term, overwritten in-place with w2
__device__ float g_asrc[NN * 4];
__device__ float g_adst[NN * 4];
__device__ float g_buf1[NN * HC];
__device__ float g_buf2[NN * HC];

#define SCB 256
#define NSB ((NN + SCB - 1) / SCB)    // 196
__device__ int g_bsum[NSB];

__device__ __forceinline__ float elu1(float v) {
    return v > 0.f ? v : (__expf(v) - 1.f);
}
__device__ __forceinline__ float expw(float l) {
    l = fmaxf(l, 0.2f * l);           // leaky relu, branchless
    return __expf(l);
}

typedef unsigned long long ull;
__device__ __forceinline__ ull ffma2(ull a, ull b, ull c) {
    ull d;
    asm("fma.rn.f32x2 %0, %1, %2, %3;" : "=l"(d) : "l"(a), "l"(b), "l"(c));
    return d;
}

// ---------------- prologue: zero degree hist + dtype probe (merged) ----------
__global__ void k_prep(const unsigned* __restrict__ ei_words) {
    int i = blockIdx.x * blockDim.x + threadIdx.x;
    if (i < NN) g_deg[i] = 0;
    if (i < 2048) {
        if (ei_words[2 * i + 1] != 0u) g_is64 = 0;
    }
}

__global__ void k_convert_hist(const void* __restrict__ ei) {
    int e = blockIdx.x * blockDim.x + threadIdx.x;
    if (e >= NE) return;
    int s, d;
    if (g_is64) {
        const long long* p = (const long long*)ei;
        s = (int)p[e]; d = (int)p[NE + e];
    } else {
        const int* p = (const int*)ei;
        s = p[e]; d = p[NE + e];
    }
    g_srce[e] = s; g_dste[e] = d;
    atomicAdd(&g_deg[d], 1);
}

// ---------------- scan stage 1: per-block sums ----------------
__global__ void k_scan1() {
    __shared__ int red[8];
    int t = threadIdx.x, lane = t & 31, wid = t >> 5;
    int i = blockIdx.x * SCB + t;
    int v = (i < NN) ? g_deg[i] : 0;
    #pragma unroll
    for (int off = 16; off; off >>= 1) v += __shfl_xor_sync(0xffffffffu, v, off);
    if (lane == 0) red[wid] = v;
    __syncthreads();
    if (t == 0) {
        int s = 0;
        #pragma unroll
        for (int j = 0; j < 8; j++) s += red[j];
        g_bsum[blockIdx.x] = s;
    }
}

// ---------------- scan stage 2+3 fused ----------------
__global__ void k_scan23() {
    __shared__ int sb[256];
    __shared__ int ws[8];
    int t = threadIdx.x, lane = t & 31, wid = t >> 5;
    sb[t] = (t < NSB) ? g_bsum[t] : 0;
    __syncthreads();
    #pragma unroll
    for (int off = 1; off < 256; off <<= 1) {
        int v = sb[t];
        int u = (t >= off) ? sb[t - off] : 0;
        __syncthreads();
        sb[t] = v + u;
        __syncthreads();
    }
    int blockoff = (blockIdx.x == 0) ? 0 : sb[blockIdx.x - 1];
    int i = blockIdx.x * SCB + t;
    int v = (i < NN) ? g_deg[i] : 0;
    int incl = v;
    #pragma unroll
    for (int off = 1; off < 32; off <<= 1) {
        int u = __shfl_up_sync(0xffffffffu, incl, off);
        if (lane >= off) incl += u;
    }
    if (lane == 31) ws[wid] = incl;
    __syncthreads();
    if (wid == 0) {
        int x = (lane < 8) ? ws[lane] : 0;
        #pragma unroll
        for (int off = 1; off < 8; off <<= 1) {
            int u = __shfl_up_sync(0xffffffffu, x, off);
            if (lane >= off) x += u;
        }
        if (lane < 8) ws[lane] = x;
    }
    __syncthreads();
    int offset = (wid ? ws[wid - 1] : 0) + blockoff;
    int excl = incl - v + offset;
    if (i < NN) { g_row[i] = excl; g_cursor[i] = excl; }
    if (i == 0) g_row[NN] = NE;
}

// ---------------- edge encoder MLP + a_e fold + layer-1 WEIGHT --------------
// Requires g_asrc/g_adst (layer 1) already computed by k_transform_small.
// Stores w1 = exp(lrelu((asrc+adst)+ae1)) directly; ae2 term kept for logit2.
__global__ void k_edge_encode(const float* __restrict__ eattr,
                              const float* __restrict__ w1, const float* __restrict__ b1,
                              const float* __restrict__ w2, const float* __restrict__ b2,
                              const float* __restrict__ We1, const float* __restrict__ aew1,
                              const float* __restrict__ We2, const float* __restrict__ aew2) {
    __shared__ float sw1[HIDC * EF];
    __shared__ float sb1[HIDC];
    __shared__ float sw2t[HIDC * NH];   // sw2t[j*4+c] = w2[c*HIDC+j]
    __shared__ float sb2[NH];
    __shared__ float sv[32];
    int t = threadIdx.x;
    if (t < HIDC * EF) sw1[t] = w1[t];
    if (t < HIDC)      sb1[t] = b1[t];
    if (t < HIDC * NH) { int j = t >> 2, c = t & 3; sw2t[t] = w2[c * HIDC + j]; }
    if (t < NH)        sb2[t] = b2[t];
    if (t < 32) {
        const float* We = (t < 16) ? We1 : We2;
        const float* aw = (t < 16) ? aew1 : aew2;
        int idx = t & 15, h = idx >> 2, k = idx & 3;
        float s = 0.f;
        for (int c = 0; c < HIDC; c++)
            s = fmaf(We[(h * HIDC + c) * NH + k], aw[h * HIDC + c], s);
        sv[t] = s;
    }
    __syncthreads();
    int e = blockIdx.x * blockDim.x + t;
    if (e >= NE) return;
    const float4* ea4 = (const float4*)(eattr + e * EF);
    float4 p0 = ea4[0], p1 = ea4[1];
    float o0 = sb2[0], o1 = sb2[1], o2 = sb2[2], o3 = sb2[3];
    #pragma unroll
    for (int j = 0; j < HIDC; j++) {
        float4 wa = *(const float4*)&sw1[j * EF];
        float4 wb = *(const float4*)&sw1[j * EF + 4];
        float h = sb1[j];
        h = fmaf(p0.x, wa.x, h); h = fmaf(p0.y, wa.y, h);
        h = fmaf(p0.z, wa.z, h); h = fmaf(p0.w, wa.w, h);
        h = fmaf(p1.x, wb.x, h); h = fmaf(p1.y, wb.y, h);
        h = fmaf(p1.z, wb.z, h); h = fmaf(p1.w, wb.w, h);
        h = fmaxf(h, 0.f);
        float4 w2v = *(const float4*)&sw2t[j * 4];
        o0 = fmaf(h, w2v.x, o0);
        o1 = fmaf(h, w2v.y, o1);
        o2 = fmaf(h, w2v.z, o2);
        o3 = fmaf(h, w2v.w, o3);
    }
    int src = g_srce[e];
    int dst = g_dste[e];
    int pos = atomicAdd(&g_cursor[dst], 1);
    g_srcs[pos] = src;
    g_dsts[pos] = dst;
    float4 r1, r2;
    r1.x = o0 * sv[0]  + o1 * sv[1]  + o2 * sv[2]  + o3 * sv[3];
    r1.y = o0 * sv[4]  + o1 * sv[5]  + o2 * sv[6]  + o3 * sv[7];
    r1.z = o0 * sv[8]  + o1 * sv[9]  + o2 * sv[10] + o3 * sv[11];
    r1.w = o0 * sv[12] + o1 * sv[13] + o2 * sv[14] + o3 * sv[15];
    r2.x = o0 * sv[16] + o1 * sv[17] + o2 * sv[18] + o3 * sv[19];
    r2.y = o0 * sv[20] + o1 * sv[21] + o2 * sv[22] + o3 * sv[23];
    r2.z = o0 * sv[24] + o1 * sv[25] + o2 * sv[26] + o3 * sv[27];
    r2.w = o0 * sv[28] + o1 * sv[29] + o2 * sv[30] + o3 * sv[31];
    // layer-1 final weights: same association as gat did: (asrc + adst) + ae
    float4 as1 = ((const float4*)g_asrc)[src];
    float4 ad1 = ((const float4*)g_adst)[dst];
    float4 wv1;
    wv1.x = expw(as1.x + ad1.x + r1.x);
    wv1.y = expw(as1.y + ad1.y + r1.y);
    wv1.z = expw(as1.z + ad1.z + r1.z);
    wv1.w = expw(as1.w + ad1.w + r1.w);
    ((float4*)g_ae1)[pos] = wv1;
    ((float4*)g_ae2)[pos] = r2;
}

// ---------------- layer-2 weights: w2 = exp(lrelu((asrc+adst)+ae2)) ---------
// In-place on g_ae2; runs after k_transform_big refreshed g_asrc/g_adst.
__global__ void k_logit2() {
    int e = blockIdx.x * blockDim.x + threadIdx.x;
    if (e >= NE) return;
    int s = g_srcs[e], d = g_dsts[e];
    float4 av = ((const float4*)g_ae2)[e];
    float4 as = __ldg(&((const float4*)g_asrc)[s]);
    float4 ad = __ldg(&((const float4*)g_adst)[d]);
    float4 w;
    w.x = expw(as.x + ad.x + av.x);
    w.y = expw(as.y + ad.y + av.y);
    w.z = expw(as.z + ad.z + av.z);
    w.w = expw(as.w + ad.w + av.w);
    ((float4*)g_ae2)[e] = w;
}

// ---------------- xp = x @ W.T (FIN=16), warp = node, lane = 4 channels -----
#define TS_BLOCKS 1250
#define TS_ITERS  (NN / (TS_BLOCKS * 8))   // 5
__global__ __launch_bounds__(256) void k_transform_small(
        const float* __restrict__ xin, const float* __restrict__ W,
        const float* __restrict__ as_w, const float* __restrict__ ad_w,
        float* __restrict__ out) {
    __shared__ float Ws[FIN * HC];      // Ws[k*128 + c] = W[c*16 + k]
    __shared__ float sas[HC], sad[HC];
    int t = threadIdx.x;   // 256
    for (int i = t; i < HC * FIN; i += 256) {
        int k = i >> 7, c = i & 127;
        Ws[i] = W[c * FIN + k];
    }
    if (t < HC) { sas[t] = as_w[t]; sad[t] = ad_w[t]; }
    __syncthreads();
    int wib = t >> 5, lane = t & 31;
    const float4* Ws4 = (const float4*)Ws;
    float4 sa4 = ((const float4*)sas)[lane];
    float4 sd4 = ((const float4*)sad)[lane];
    #pragma unroll
    for (int g = 0; g < TS_ITERS; g++) {
        int n = (g * TS_BLOCKS + blockIdx.x) * 8 + wib;
        const float4* xr = (const float4*)(xin + n * FIN);
        float4 x0 = xr[0], x1 = xr[1], x2 = xr[2], x3 = xr[3];  // broadcast
        float xk[16] = {x0.x, x0.y, x0.z, x0.w, x1.x, x1.y, x1.z, x1.w,
                        x2.x, x2.y, x2.z, x2.w, x3.x, x3.y, x3.z, x3.w};
        float4 acc = make_float4(0.f, 0.f, 0.f, 0.f);
        #pragma unroll
        for (int k = 0; k < FIN; k++) {
            float4 wv = Ws4[k * 32 + lane];
            acc.x = fmaf(xk[k], wv.x, acc.x);
            acc.y = fmaf(xk[k], wv.y, acc.y);
            acc.z = fmaf(xk[k], wv.z, acc.z);
            acc.w = fmaf(xk[k], wv.w, acc.w);
        }
        ((float4*)(out + n * HC))[lane] = acc;
        float ps = acc.x * sa4.x + acc.y * sa4.y + acc.z * sa4.z + acc.w * sa4.w;
        float pd = acc.x * sd4.x + acc.y * sd4.y + acc.z * sd4.z + acc.w * sd4.w;
        #pragma unroll
        for (int off = 1; off < 8; off <<= 1) {
            ps += __shfl_xor_sync(0xffffffffu, ps, off);
            pd += __shfl_xor_sync(0xffffffffu, pd, off);
        }
        if ((lane & 7) == 0) {
            int h = lane >> 3;
            g_asrc[n * 4 + h] = ps;
            g_adst[n * 4 + h] = pd;
        }
    }
}

// ---------------- xp = h @ W.T (128->128), conflict-free (R10) --------------
#define TMB   128
#define XPAD  132
#define SMEM_BIG ((HC * HC + TMB * XPAD + 2 * HC + 2 * 16 * HC) * 4)
__global__ __launch_bounds__(512, 1) void k_transform_big(
        const float* __restrict__ hin, const float* __restrict__ W,
        const float* __restrict__ as_w, const float* __restrict__ ad_w,
        float* __restrict__ out) {
    extern __shared__ float smem[];
    float* Wt  = smem;                     // [c][k] native, 64 KB
    float* xs  = smem + HC * HC;           // [nl][XPAD]
    float* sas = xs + TMB * XPAD;
    float* sad = sas + HC;
    float* sps = sad + HC;                 // [16][128] a_src partials
    float* spd = sps + 16 * HC;            // [16][128] a_dst partials
    int t = threadIdx.x;
    int n0 = blockIdx.x * TMB;
    for (int i = t; i < HC * HC; i += 512) Wt[i] = W[i];       // pure copy
    for (int i = t; i < TMB * HC; i += 512) {
        int nl = i >> 7, k = i & 127, n = n0 + nl;
        xs[nl * XPAD + k] = (n < NN) ? hin[n * HC + k] : 0.f;
    }
    if (t < HC) { sas[t] = as_w[t]; sad[t] = ad_w[t]; }
    __syncthreads();
    int lane = t & 31, w = t >> 5;
    int ng = w & 1;
    int nd0 = ng * 32 + lane, nd1 = (ng + 2) * 32 + lane;
    const float* xr0 = xs + nd0 * XPAD;
    const float* xr1 = xs + nd1 * XPAD;
    int gn0 = n0 + nd0, gn1 = n0 + nd1;
    #pragma unroll 1
    for (int tile = 0; tile < 2; tile++) {
        int cg = (w >> 1) + 8 * tile;
        const float* wbase = Wt + cg * 8 * HC;
        ull acc0[8], acc1[8];
        #pragma unroll
        for (int j = 0; j < 8; j++) { acc0[j] = 0ull; acc1[j] = 0ull; }
        #pragma unroll 4
        for (int k = 0; k < HC; k += 4) {
            ulonglong2 xv0 = *(const ulonglong2*)(xr0 + k);
            ulonglong2 xv1 = *(const ulonglong2*)(xr1 + k);
            #pragma unroll
            for (int j = 0; j < 8; j++) {
                ulonglong2 wv = *(const ulonglong2*)(wbase + j * HC + k);
                acc0[j] = ffma2(xv0.x, wv.x, acc0[j]);
                acc0[j] = ffma2(xv0.y, wv.y, acc0[j]);
                acc1[j] = ffma2(xv1.x, wv.x, acc1[j]);
                acc1[j] = ffma2(xv1.y, wv.y, acc1[j]);
            }
        }
        float a0[8], a1[8];
        #pragma unroll
        for (int j = 0; j < 8; j++) {
            float2 f0 = *(float2*)&acc0[j];
            float2 f1 = *(float2*)&acc1[j];
            a0[j] = f0.x + f0.y;
            a1[j] = f1.x + f1.y;
        }
        if (gn0 < NN) {
            float4* o4 = (float4*)(out + gn0 * HC + cg * 8);
            o4[0] = make_float4(a0[0], a0[1], a0[2], a0[3]);
            o4[1] = make_float4(a0[4], a0[5], a0[6], a0[7]);
        }
        if (gn1 < NN) {
            float4* o4 = (float4*)(out + gn1 * HC + cg * 8);
            o4[0] = make_float4(a1[0], a1[1], a1[2], a1[3]);
            o4[1] = make_float4(a1[4], a1[5], a1[6], a1[7]);
        }
        float ps0 = 0.f, pd0 = 0.f, ps1 = 0.f, pd1 = 0.f;
        #pragma unroll
        for (int j = 0; j < 8; j++) {
            float sa = sas[cg * 8 + j], sd = sad[cg * 8 + j];
            ps0 = fmaf(a0[j], sa, ps0);  pd0 = fmaf(a0[j], sd, pd0);
            ps1 = fmaf(a1[j], sa, ps1);  pd1 = fmaf(a1[j], sd, pd1);
        }
        sps[cg * HC + nd0] = ps0;  spd[cg * HC + nd0] = pd0;
        sps[cg * HC + nd1] = ps1;  spd[cg * HC + nd1] = pd1;
    }
    __syncthreads();
    {
        int node = t & 127, h = t >> 7;
        int n = n0 + node;
        float ps = 0.f, pd = 0.f;
        #pragma unroll
        for (int j = 0; j < 4; j++) {
            ps += sps[(h * 4 + j) * HC + node];
            pd += spd[(h * 4 + j) * HC + node];
        }
        if (n < NN) { g_asrc[n * 4 + h] = ps; g_adst[n * 4 + h] = pd; }
    }
}

// ---------------- layer-1 gat: lean (weights precomputed) -------------------
__global__ void k_gat(const float* __restrict__ xp,
                      const float* __restrict__ wgt,
                      const float* __restrict__ bias,
                      float* __restrict__ out) {
    int warp = (blockIdx.x * blockDim.x + threadIdx.x) >> 5;
    int lane = threadIdx.x & 31;
    if (warp >= NN) return;
    int n = warp;
    int row = __ldg(&g_row[n]), end = __ldg(&g_row[n + 1]);
    int h = lane >> 3;
    float ax = 0.f, ay = 0.f, az = 0.f, aw = 0.f, wsum = 0.f;
    for (int base = row; base < end; base += 8) {
        int m = end - base;
        int s[8];
        float wv[8];
        #pragma unroll
        for (int j = 0; j < 8; j++) {
            int jc = (j < m) ? j : 0;
            s[j]  = __ldg(&g_srcs[base + jc]);
            wv[j] = __ldg(&wgt[(base + jc) * 4 + h]);   // no src dependency
        }
        float4 xv[8];
        #pragma unroll
        for (int j = 0; j < 8; j++)
            xv[j] = __ldg(&((const float4*)(xp + s[j] * HC))[lane]);
        #pragma unroll
        for (int j = 0; j < 8; j++) {
            float w = (j < m) ? wv[j] : 0.f;
            ax = fmaf(w, xv[j].x, ax);
            ay = fmaf(w, xv[j].y, ay);
            az = fmaf(w, xv[j].z, az);
            aw = fmaf(w, xv[j].w, aw);
            wsum += w;
        }
    }
    float inv = 1.f / (wsum + 1e-16f);
    float4 b4 = __ldg(&((const float4*)bias)[lane]);
    float4 o;
    o.x = elu1(ax * inv + b4.x);
    o.y = elu1(ay * inv + b4.y);
    o.z = elu1(az * inv + b4.z);
    o.w = elu1(aw * inv + b4.w);
    ((float4*)(out + n * HC))[lane] = o;
}

// ---------------- layer-2 gat + fused skip/classifier: lean -----------------
__global__ __launch_bounds__(256) void k_gat2_final(
        const float* __restrict__ xp, const float* __restrict__ wgt,
        const float* __restrict__ bias,
        const float* __restrict__ x,
        const float* __restrict__ skip_w, const float* __restrict__ skip_b,
        const float* __restrict__ cls_w, const float* __restrict__ cls_b,
        float* __restrict__ out) {
    __shared__ float swT[FIN * HC];     // swT[k*128+c] = skip_w[c*16+k]
    __shared__ float scw[NCLS * HC];
    int t = threadIdx.x;   // 256, grid = NN/8 exactly -> all warps valid
    for (int i = t; i < FIN * HC; i += 256) {
        int k = i >> 7, c = i & 127;
        swT[i] = skip_w[c * FIN + k];
    }
    for (int i = t; i < NCLS * HC; i += 256) scw[i] = cls_w[i];
    __syncthreads();
    int n = blockIdx.x * 8 + (t >> 5);
    int lane = t & 31;
    int row = __ldg(&g_row[n]), end = __ldg(&g_row[n + 1]);
    int h = lane >> 3;
    float ax = 0.f, ay = 0.f, az = 0.f, aw = 0.f, wsum = 0.f;
    for (int base = row; base < end; base += 8) {
        int m = end - base;
        int s[8];
        float wv[8];
        #pragma unroll
        for (int j = 0; j < 8; j++) {
            int jc = (j < m) ? j : 0;
            s[j]  = __ldg(&g_srcs[base + jc]);
            wv[j] = __ldg(&wgt[(base + jc) * 4 + h]);
        }
        float4 xv[8];
        #pragma unroll
        for (int j = 0; j < 8; j++)
            xv[j] = __ldg(&((const float4*)(xp + s[j] * HC))[lane]);
        #pragma unroll
        for (int j = 0; j < 8; j++) {
            float w = (j < m) ? wv[j] : 0.f;
            ax = fmaf(w, xv[j].x, ax);
            ay = fmaf(w, xv[j].y, ay);
            az = fmaf(w, xv[j].z, az);
            aw = fmaf(w, xv[j].w, aw);
            wsum += w;
        }
    }
    float inv = 1.f / (wsum + 1e-16f);
    float4 b4 = __ldg(&((const float4*)bias)[lane]);
    float4 hv;
    hv.x = elu1(ax * inv + b4.x);
    hv.y = elu1(ay * inv + b4.y);
    hv.z = elu1(az * inv + b4.z);
    hv.w = elu1(aw * inv + b4.w);
    // ---- fused skip + classifier (same arithmetic as before) ----
    const float4* xr = (const float4*)(x + n * FIN);
    float4 x0 = xr[0], x1 = xr[1], x2 = xr[2], x3 = xr[3];
    float xk[16] = {x0.x, x0.y, x0.z, x0.w, x1.x, x1.y, x1.z, x1.w,
                    x2.x, x2.y, x2.z, x2.w, x3.x, x3.y, x3.z, x3.w};
    const float4* swT4 = (const float4*)swT;
    const float4* scw4 = (const float4*)scw;
    float4 sk = ((const float4*)skip_b)[lane];
    #pragma unroll
    for (int k = 0; k < FIN; k++) {
        float4 wv = swT4[k * 32 + lane];
        sk.x = fmaf(xk[k], wv.x, sk.x);
        sk.y = fmaf(xk[k], wv.y, sk.y);
        sk.z = fmaf(xk[k], wv.z, sk.z);
        sk.w = fmaf(xk[k], wv.w, sk.w);
    }
    float4 v = make_float4(hv.x + sk.x, hv.y + sk.y, hv.z + sk.z, hv.w + sk.w);
    float p[NCLS];
    #pragma unroll
    for (int c = 0; c < NCLS; c++) {
        float4 cw = scw4[c * 32 + lane];
        p[c] = v.x * cw.x + v.y * cw.y + v.z * cw.z + v.w * cw.w;
        #pragma unroll
        for (int off = 16; off; off >>= 1)
            p[c] += __shfl_xor_sync(0xffffffffu, p[c], off);
    }
    if (lane < NCLS) out[n * NCLS + lane] = p[lane] + cls_b[lane];
}

extern "C" void kernel_launch(void* const* d_in, const int* in_sizes, int n_in,
                              void* d_out, int out_size) {
    const float* x      = (const float*)d_in[0];
    const void*  ei     = d_in[1];
    const float* eattr  = (const float*)d_in[2];
    const float* ee_w1  = (const float*)d_in[3];
    const float* ee_b1  = (const float*)d_in[4];
    const float* ee_w2  = (const float*)d_in[5];
    const float* ee_b2  = (const float*)d_in[6];
    const float* g1_W   = (const float*)d_in[7];
    const float* g1_We  = (const float*)d_in[8];
    const float* g1_as  = (const float*)d_in[9];
    const float* g1_ad  = (const float*)d_in[10];
    const float* g1_ae  = (const float*)d_in[11];
    const float* g1_b   = (const float*)d_in[12];
    const float* g2_W   = (const float*)d_in[13];
    const float* g2_We  = (const float*)d_in[14];
    const float* g2_as  = (const float*)d_in[15];
    const float* g2_ad  = (const float*)d_in[16];
    const float* g2_ae  = (const float*)d_in[17];
    const float* g2_b   = (const float*)d_in[18];
    const float* skip_w = (const float*)d_in[19];
    const float* skip_b = (const float*)d_in[20];
    const float* cls_w  = (const float*)d_in[21];
    const float* cls_b  = (const float*)d_in[22];
    float* out = (float*)d_out;

    static_assert(SMEM_BIG <= 227 * 1024, "smem");
    cudaFuncSetAttribute(k_transform_big, cudaFuncAttributeMaxDynamicSharedMemorySize, SMEM_BIG);

    float *buf1, *buf2, *w1buf, *w2buf;
    cudaGetSymbolAddress((void**)&buf1, g_buf1);
    cudaGetSymbolAddress((void**)&buf2, g_buf2);
    cudaGetSymbolAddress((void**)&w1buf, g_ae1);
    cudaGetSymbolAddress((void**)&w2buf, g_ae2);

    // launches (tsmall 4th: ncu's fixed capture slot; must precede encode
    // because encode consumes layer-1 g_asrc/g_adst)
    k_prep<<<NSB, SCB>>>((const unsigned*)ei);                          // 1
    k_convert_hist<<<NE / 256, 256>>>(ei);                              // 2
    k_scan1<<<NSB, SCB>>>();                                            // 3
    k_transform_small<<<TS_BLOCKS, 256>>>(x, g1_W, g1_as, g1_ad, buf1); // 4
    k_scan23<<<NSB, SCB>>>();                                           // 5
    k_edge_encode<<<NE / 256, 256>>>(eattr, ee_w1, ee_b1, ee_w2, ee_b2,
                                     g1_We, g1_ae, g2_We, g2_ae);       // 6
    // --- layer 1 (weights precomputed in encode) ---
    k_gat<<<(NN * 32 + 255) / 256, 256>>>(buf1, w1buf, g1_b, buf2);     // 7
    // --- layer 2 ---
    k_transform_big<<<(NN + TMB - 1) / TMB, 512, SMEM_BIG>>>(buf2, g2_W, g2_as, g2_ad, buf1); // 8
    k_logit2<<<NE / 256, 256>>>();                                      // 9
    k_gat2_final<<<NN / 8, 256>>>(buf1, w2buf, g2_b,
                                  x, skip_w, skip_b, cls_w, cls_b, out); // 10
}

// round 15
// speedup vs baseline: 1.3674x; 1.0066x over previous
#include <cuda_runtime.h>

#define NN   50000
#define NE   800000
#define FIN  16
#define HIDC 32
#define NH   4
#define HC   128
#define NCLS 5
#define EF   8

// ---------------- scratch (static device allocation; no cudaMalloc) ----------
__device__ int   g_is64 = 1;          // probe only ever writes 0 -> deterministic
__device__ int   g_deg[NN];
__device__ int   g_cursor[NN];
__device__ int   g_row[NN + 1];
__device__ int   g_srce[NE];
__device__ int   g_dste[NE];
__device__ int   g_srcs[NE];          // src ids sorted by dst
__device__ int   g_dsts[NE];          // dst ids sorted by dst (for layer-2 logits)
__device__ float g_ae1[NE * 4];       // layer-1: final softmax weights w1 (sorted)
__device__ float g_ae2[NE * 4];       // layer-2: ae term, overwritten in-place with w2
__device__ float g_asrc[NN * 4];
__device__ float g_adst[NN * 4];
__device__ float g_buf1[NN * HC];
__device__ float g_buf2[NN * HC];

#define SCB 256
#define NSB ((NN + SCB - 1) / SCB)    // 196
__device__ int g_bsum[NSB];

__device__ __forceinline__ float elu1(float v) {
    return v > 0.f ? v : (__expf(v) - 1.f);
}
__device__ __forceinline__ float expw(float l) {
    l = fmaxf(l, 0.2f * l);           // leaky relu, branchless
    return __expf(l);
}

typedef unsigned long long ull;
__device__ __forceinline__ ull ffma2(ull a, ull b, ull c) {
    ull d;
    asm("fma.rn.f32x2 %0, %1, %2, %3;" : "=l"(d) : "l"(a), "l"(b), "l"(c));
    return d;
}

// ---------------- prologue: zero degree hist + dtype probe (merged) ----------
__global__ void k_prep(const unsigned* __restrict__ ei_words) {
    int i = blockIdx.x * blockDim.x + threadIdx.x;
    if (i < NN) g_deg[i] = 0;
    if (i < 2048) {
        if (ei_words[2 * i + 1] != 0u) g_is64 = 0;
    }
}

__global__ void k_convert_hist(const void* __restrict__ ei) {
    int e = blockIdx.x * blockDim.x + threadIdx.x;
    if (e >= NE) return;
    int s, d;
    if (g_is64) {
        const long long* p = (const long long*)ei;
        s = (int)p[e]; d = (int)p[NE + e];
    } else {
        const int* p = (const int*)ei;
        s = p[e]; d = p[NE + e];
    }
    g_srce[e] = s; g_dste[e] = d;
    atomicAdd(&g_deg[d], 1);
}

// ---------------- scan stage 1: per-block sums ----------------
__global__ void k_scan1() {
    __shared__ int red[8];
    int t = threadIdx.x, lane = t & 31, wid = t >> 5;
    int i = blockIdx.x * SCB + t;
    int v = (i < NN) ? g_deg[i] : 0;
    #pragma unroll
    for (int off = 16; off; off >>= 1) v += __shfl_xor_sync(0xffffffffu, v, off);
    if (lane == 0) red[wid] = v;
    __syncthreads();
    if (t == 0) {
        int s = 0;
        #pragma unroll
        for (int j = 0; j < 8; j++) s += red[j];
        g_bsum[blockIdx.x] = s;
    }
}

// ---------------- scan stage 2+3 fused ----------------
__global__ void k_scan23() {
    __shared__ int sb[256];
    __shared__ int ws[8];
    int t = threadIdx.x, lane = t & 31, wid = t >> 5;
    sb[t] = (t < NSB) ? g_bsum[t] : 0;
    __syncthreads();
    #pragma unroll
    for (int off = 1; off < 256; off <<= 1) {
        int v = sb[t];
        int u = (t >= off) ? sb[t - off] : 0;
        __syncthreads();
        sb[t] = v + u;
        __syncthreads();
    }
    int blockoff = (blockIdx.x == 0) ? 0 : sb[blockIdx.x - 1];
    int i = blockIdx.x * SCB + t;
    int v = (i < NN) ? g_deg[i] : 0;
    int incl = v;
    #pragma unroll
    for (int off = 1; off < 32; off <<= 1) {
        int u = __shfl_up_sync(0xffffffffu, incl, off);
        if (lane >= off) incl += u;
    }
    if (lane == 31) ws[wid] = incl;
    __syncthreads();
    if (wid == 0) {
        int x = (lane < 8) ? ws[lane] : 0;
        #pragma unroll
        for (int off = 1; off < 8; off <<= 1) {
            int u = __shfl_up_sync(0xffffffffu, x, off);
            if (lane >= off) x += u;
        }
        if (lane < 8) ws[lane] = x;
    }
    __syncthreads();
    int offset = (wid ? ws[wid - 1] : 0) + blockoff;
    int excl = incl - v + offset;
    if (i < NN) { g_row[i] = excl; g_cursor[i] = excl; }
    if (i == 0) g_row[NN] = NE;
}

// ---------------- edge encoder MLP + a_e fold + layer-1 WEIGHT --------------
// Requires g_asrc/g_adst (layer 1) already computed by k_transform_small.
__global__ void k_edge_encode(const float* __restrict__ eattr,
                              const float* __restrict__ w1, const float* __restrict__ b1,
                              const float* __restrict__ w2, const float* __restrict__ b2,
                              const float* __restrict__ We1, const float* __restrict__ aew1,
                              const float* __restrict__ We2, const float* __restrict__ aew2) {
    __shared__ float sw1[HIDC * EF];
    __shared__ float sb1[HIDC];
    __shared__ float sw2t[HIDC * NH];   // sw2t[j*4+c] = w2[c*HIDC+j]
    __shared__ float sb2[NH];
    __shared__ float sv[32];
    int t = threadIdx.x;
    if (t < HIDC * EF) sw1[t] = w1[t];
    if (t < HIDC)      sb1[t] = b1[t];
    if (t < HIDC * NH) { int j = t >> 2, c = t & 3; sw2t[t] = w2[c * HIDC + j]; }
    if (t < NH)        sb2[t] = b2[t];
    if (t < 32) {
        const float* We = (t < 16) ? We1 : We2;
        const float* aw = (t < 16) ? aew1 : aew2;
        int idx = t & 15, h = idx >> 2, k = idx & 3;
        float s = 0.f;
        for (int c = 0; c < HIDC; c++)
            s = fmaf(We[(h * HIDC + c) * NH + k], aw[h * HIDC + c], s);
        sv[t] = s;
    }
    __syncthreads();
    int e = blockIdx.x * blockDim.x + t;
    if (e >= NE) return;
    const float4* ea4 = (const float4*)(eattr + e * EF);
    float4 p0 = ea4[0], p1 = ea4[1];
    float o0 = sb2[0], o1 = sb2[1], o2 = sb2[2], o3 = sb2[3];
    #pragma unroll
    for (int j = 0; j < HIDC; j++) {
        float4 wa = *(const float4*)&sw1[j * EF];
        float4 wb = *(const float4*)&sw1[j * EF + 4];
        float h = sb1[j];
        h = fmaf(p0.x, wa.x, h); h = fmaf(p0.y, wa.y, h);
        h = fmaf(p0.z, wa.z, h); h = fmaf(p0.w, wa.w, h);
        h = fmaf(p1.x, wb.x, h); h = fmaf(p1.y, wb.y, h);
        h = fmaf(p1.z, wb.z, h); h = fmaf(p1.w, wb.w, h);
        h = fmaxf(h, 0.f);
        float4 w2v = *(const float4*)&sw2t[j * 4];
        o0 = fmaf(h, w2v.x, o0);
        o1 = fmaf(h, w2v.y, o1);
        o2 = fmaf(h, w2v.z, o2);
        o3 = fmaf(h, w2v.w, o3);
    }
    int src = g_srce[e];
    int dst = g_dste[e];
    int pos = atomicAdd(&g_cursor[dst], 1);
    g_srcs[pos] = src;
    g_dsts[pos] = dst;
    float4 r1, r2;
    r1.x = o0 * sv[0]  + o1 * sv[1]  + o2 * sv[2]  + o3 * sv[3];
    r1.y = o0 * sv[4]  + o1 * sv[5]  + o2 * sv[6]  + o3 * sv[7];
    r1.z = o0 * sv[8]  + o1 * sv[9]  + o2 * sv[10] + o3 * sv[11];
    r1.w = o0 * sv[12] + o1 * sv[13] + o2 * sv[14] + o3 * sv[15];
    r2.x = o0 * sv[16] + o1 * sv[17] + o2 * sv[18] + o3 * sv[19];
    r2.y = o0 * sv[20] + o1 * sv[21] + o2 * sv[22] + o3 * sv[23];
    r2.z = o0 * sv[24] + o1 * sv[25] + o2 * sv[26] + o3 * sv[27];
    r2.w = o0 * sv[28] + o1 * sv[29] + o2 * sv[30] + o3 * sv[31];
    // layer-1 final weights: (asrc + adst) + ae, as in the original gat
    float4 as1 = ((const float4*)g_asrc)[src];
    float4 ad1 = ((const float4*)g_adst)[dst];
    float4 wv1;
    wv1.x = expw(as1.x + ad1.x + r1.x);
    wv1.y = expw(as1.y + ad1.y + r1.y);
    wv1.z = expw(as1.z + ad1.z + r1.z);
    wv1.w = expw(as1.w + ad1.w + r1.w);
    ((float4*)g_ae1)[pos] = wv1;
    ((float4*)g_ae2)[pos] = r2;
}

// ---------------- layer-2 weights: w2 = exp(lrelu((asrc+adst)+ae2)) ---------
__global__ void k_logit2() {
    int e = blockIdx.x * blockDim.x + threadIdx.x;
    if (e >= NE) return;
    int s = g_srcs[e], d = g_dsts[e];
    float4 av = ((const float4*)g_ae2)[e];
    float4 as = __ldg(&((const float4*)g_asrc)[s]);
    float4 ad = __ldg(&((const float4*)g_adst)[d]);
    float4 w;
    w.x = expw(as.x + ad.x + av.x);
    w.y = expw(as.y + ad.y + av.y);
    w.z = expw(as.z + ad.z + av.z);
    w.w = expw(as.w + ad.w + av.w);
    ((float4*)g_ae2)[e] = w;
}

// ---------------- xp = x @ W.T (FIN=16), warp = node, lane = 4 channels -----
#define TS_BLOCKS 1250
#define TS_ITERS  (NN / (TS_BLOCKS * 8))   // 5
__global__ __launch_bounds__(256) void k_transform_small(
        const float* __restrict__ xin, const float* __restrict__ W,
        const float* __restrict__ as_w, const float* __restrict__ ad_w,
        float* __restrict__ out) {
    __shared__ float Ws[FIN * HC];      // Ws[k*128 + c] = W[c*16 + k]
    __shared__ float sas[HC], sad[HC];
    int t = threadIdx.x;   // 256
    for (int i = t; i < HC * FIN; i += 256) {
        int k = i >> 7, c = i & 127;
        Ws[i] = W[c * FIN + k];
    }
    if (t < HC) { sas[t] = as_w[t]; sad[t] = ad_w[t]; }
    __syncthreads();
    int wib = t >> 5, lane = t & 31;
    const float4* Ws4 = (const float4*)Ws;
    float4 sa4 = ((const float4*)sas)[lane];
    float4 sd4 = ((const float4*)sad)[lane];
    #pragma unroll
    for (int g = 0; g < TS_ITERS; g++) {
        int n = (g * TS_BLOCKS + blockIdx.x) * 8 + wib;
        const float4* xr = (const float4*)(xin + n * FIN);
        float4 x0 = xr[0], x1 = xr[1], x2 = xr[2], x3 = xr[3];  // broadcast
        float xk[16] = {x0.x, x0.y, x0.z, x0.w, x1.x, x1.y, x1.z, x1.w,
                        x2.x, x2.y, x2.z, x2.w, x3.x, x3.y, x3.z, x3.w};
        float4 acc = make_float4(0.f, 0.f, 0.f, 0.f);
        #pragma unroll
        for (int k = 0; k < FIN; k++) {
            float4 wv = Ws4[k * 32 + lane];
            acc.x = fmaf(xk[k], wv.x, acc.x);
            acc.y = fmaf(xk[k], wv.y, acc.y);
            acc.z = fmaf(xk[k], wv.z, acc.z);
            acc.w = fmaf(xk[k], wv.w, acc.w);
        }
        ((float4*)(out + n * HC))[lane] = acc;
        float ps = acc.x * sa4.x + acc.y * sa4.y + acc.z * sa4.z + acc.w * sa4.w;
        float pd = acc.x * sd4.x + acc.y * sd4.y + acc.z * sd4.z + acc.w * sd4.w;
        #pragma unroll
        for (int off = 1; off < 8; off <<= 1) {
            ps += __shfl_xor_sync(0xffffffffu, ps, off);
            pd += __shfl_xor_sync(0xffffffffu, pd, off);
        }
        if ((lane & 7) == 0) {
            int h = lane >> 3;
            g_asrc[n * 4 + h] = ps;
            g_adst[n * 4 + h] = pd;
        }
    }
}

// ---------------- xp = h @ W.T (128->128), conflict-free (R10) --------------
#define TMB   128
#define XPAD  132
#define SMEM_BIG ((HC * HC + TMB * XPAD + 2 * HC + 2 * 16 * HC) * 4)
__global__ __launch_bounds__(512, 1) void k_transform_big(
        const float* __restrict__ hin, const float* __restrict__ W,
        const float* __restrict__ as_w, const float* __restrict__ ad_w,
        float* __restrict__ out) {
    extern __shared__ float smem[];
    float* Wt  = smem;                     // [c][k] native, 64 KB
    float* xs  = smem + HC * HC;           // [nl][XPAD]
    float* sas = xs + TMB * XPAD;
    float* sad = sas + HC;
    float* sps = sad + HC;                 // [16][128] a_src partials
    float* spd = sps + 16 * HC;            // [16][128] a_dst partials
    int t = threadIdx.x;
    int n0 = blockIdx.x * TMB;
    for (int i = t; i < HC * HC; i += 512) Wt[i] = W[i];       // pure copy
    for (int i = t; i < TMB * HC; i += 512) {
        int nl = i >> 7, k = i & 127, n = n0 + nl;
        xs[nl * XPAD + k] = (n < NN) ? hin[n * HC + k] : 0.f;
    }
    if (t < HC) { sas[t] = as_w[t]; sad[t] = ad_w[t]; }
    __syncthreads();
    int lane = t & 31, w = t >> 5;
    int ng = w & 1;
    int nd0 = ng * 32 + lane, nd1 = (ng + 2) * 32 + lane;
    const float* xr0 = xs + nd0 * XPAD;
    const float* xr1 = xs + nd1 * XPAD;
    int gn0 = n0 + nd0, gn1 = n0 + nd1;
    #pragma unroll 1
    for (int tile = 0; tile < 2; tile++) {
        int cg = (w >> 1) + 8 * tile;
        const float* wbase = Wt + cg * 8 * HC;
        ull acc0[8], acc1[8];
        #pragma unroll
        for (int j = 0; j < 8; j++) { acc0[j] = 0ull; acc1[j] = 0ull; }
        #pragma unroll 4
        for (int k = 0; k < HC; k += 4) {
            ulonglong2 xv0 = *(const ulonglong2*)(xr0 + k);
            ulonglong2 xv1 = *(const ulonglong2*)(xr1 + k);
            #pragma unroll
            for (int j = 0; j < 8; j++) {
                ulonglong2 wv = *(const ulonglong2*)(wbase + j * HC + k);
                acc0[j] = ffma2(xv0.x, wv.x, acc0[j]);
                acc0[j] = ffma2(xv0.y, wv.y, acc0[j]);
                acc1[j] = ffma2(xv1.x, wv.x, acc1[j]);
                acc1[j] = ffma2(xv1.y, wv.y, acc1[j]);
            }
        }
        float a0[8], a1[8];
        #pragma unroll
        for (int j = 0; j < 8; j++) {
            float2 f0 = *(float2*)&acc0[j];
            float2 f1 = *(float2*)&acc1[j];
            a0[j] = f0.x + f0.y;
            a1[j] = f1.x + f1.y;
        }
        if (gn0 < NN) {
            float4* o4 = (float4*)(out + gn0 * HC + cg * 8);
            o4[0] = make_float4(a0[0], a0[1], a0[2], a0[3]);
            o4[1] = make_float4(a0[4], a0[5], a0[6], a0[7]);
        }
        if (gn1 < NN) {
            float4* o4 = (float4*)(out + gn1 * HC + cg * 8);
            o4[0] = make_float4(a1[0], a1[1], a1[2], a1[3]);
            o4[1] = make_float4(a1[4], a1[5], a1[6], a1[7]);
        }
        float ps0 = 0.f, pd0 = 0.f, ps1 = 0.f, pd1 = 0.f;
        #pragma unroll
        for (int j = 0; j < 8; j++) {
            float sa = sas[cg * 8 + j], sd = sad[cg * 8 + j];
            ps0 = fmaf(a0[j], sa, ps0);  pd0 = fmaf(a0[j], sd, pd0);
            ps1 = fmaf(a1[j], sa, ps1);  pd1 = fmaf(a1[j], sd, pd1);
        }
        sps[cg * HC + nd0] = ps0;  spd[cg * HC + nd0] = pd0;
        sps[cg * HC + nd1] = ps1;  spd[cg * HC + nd1] = pd1;
    }
    __syncthreads();
    {
        int node = t & 127, h = t >> 7;
        int n = n0 + node;
        float ps = 0.f, pd = 0.f;
        #pragma unroll
        for (int j = 0; j < 4; j++) {
            ps += sps[(h * 4 + j) * HC + node];
            pd += spd[(h * 4 + j) * HC + node];
        }
        if (n < NN) { g_asrc[n * 4 + h] = ps; g_adst[n * 4 + h] = pd; }
    }
}

// ---------------- layer-1 gat: lean, tail-predicated ------------------------
__global__ void k_gat(const float* __restrict__ xp,
                      const float* __restrict__ wgt,
                      const float* __restrict__ bias,
                      float* __restrict__ out) {
    int warp = (blockIdx.x * blockDim.x + threadIdx.x) >> 5;
    int lane = threadIdx.x & 31;
    if (warp >= NN) return;
    int n = warp;
    int row = __ldg(&g_row[n]), end = __ldg(&g_row[n + 1]);
    int h = lane >> 3;
    float ax = 0.f, ay = 0.f, az = 0.f, aw = 0.f, wsum = 0.f;
    for (int base = row; base < end; base += 8) {
        int m = end - base;
        int s[8];
        float wv[8];
        #pragma unroll
        for (int j = 0; j < 8; j++) {
            s[j] = 0; wv[j] = 0.f;
            if (j < m) {
                s[j]  = __ldg(&g_srcs[base + j]);
                wv[j] = __ldg(&wgt[(base + j) * 4 + h]);
            }
        }
        float4 xv[8];
        #pragma unroll
        for (int j = 0; j < 8; j++) {
            xv[j] = make_float4(0.f, 0.f, 0.f, 0.f);
            if (j < m)
                xv[j] = __ldg(&((const float4*)(xp + s[j] * HC))[lane]);
        }
        #pragma unroll
        for (int j = 0; j < 8; j++) {
            float w = wv[j];
            ax = fmaf(w, xv[j].x, ax);
            ay = fmaf(w, xv[j].y, ay);
            az = fmaf(w, xv[j].z, az);
            aw = fmaf(w, xv[j].w, aw);
            wsum += w;
        }
    }
    float inv = 1.f / (wsum + 1e-16f);
    float4 b4 = __ldg(&((const float4*)bias)[lane]);
    float4 o;
    o.x = elu1(ax * inv + b4.x);
    o.y = elu1(ay * inv + b4.y);
    o.z = elu1(az * inv + b4.z);
    o.w = elu1(aw * inv + b4.w);
    ((float4*)(out + n * HC))[lane] = o;
}

// ---------------- layer-2 gat + fused skip/classifier: tail-predicated ------
__global__ __launch_bounds__(256) void k_gat2_final(
        const float* __restrict__ xp, const float* __restrict__ wgt,
        const float* __restrict__ bias,
        const float* __restrict__ x,
        const float* __restrict__ skip_w, const float* __restrict__ skip_b,
        const float* __restrict__ cls_w, const float* __restrict__ cls_b,
        float* __restrict__ out) {
    __shared__ float swT[FIN * HC];     // swT[k*128+c] = skip_w[c*16+k]
    __shared__ float scw[NCLS * HC];
    int t = threadIdx.x;   // 256, grid = NN/8 exactly -> all warps valid
    for (int i = t; i < FIN * HC; i += 256) {
        int k = i >> 7, c = i & 127;
        swT[i] = skip_w[c * FIN + k];
    }
    for (int i = t; i < NCLS * HC; i += 256) scw[i] = cls_w[i];
    __syncthreads();
    int n = blockIdx.x * 8 + (t >> 5);
    int lane = t & 31;
    int row = __ldg(&g_row[n]), end = __ldg(&g_row[n + 1]);
    int h = lane >> 3;
    float ax = 0.f, ay = 0.f, az = 0.f, aw = 0.f, wsum = 0.f;
    for (int base = row; base < end; base += 8) {
        int m = end - base;
        int s[8];
        float wv[8];
        #pragma unroll
        for (int j = 0; j < 8; j++) {
            s[j] = 0; wv[j] = 0.f;
            if (j < m) {
                s[j]  = __ldg(&g_srcs[base + j]);
                wv[j] = __ldg(&wgt[(base + j) * 4 + h]);
            }
        }
        float4 xv[8];
        #pragma unroll
        for (int j = 0; j < 8; j++) {
            xv[j] = make_float4(0.f, 0.f, 0.f, 0.f);
            if (j < m)
                xv[j] = __ldg(&((const float4*)(xp + s[j] * HC))[lane]);
        }
        #pragma unroll
        for (int j = 0; j < 8; j++) {
            float w = wv[j];
            ax = fmaf(w, xv[j].x, ax);
            ay = fmaf(w, xv[j].y, ay);
            az = fmaf(w, xv[j].z, az);
            aw = fmaf(w, xv[j].w, aw);
            wsum += w;
        }
    }
    float inv = 1.f / (wsum + 1e-16f);
    float4 b4 = __ldg(&((const float4*)bias)[lane]);
    float4 hv;
    hv.x = elu1(ax * inv + b4.x);
    hv.y = elu1(ay * inv + b4.y);
    hv.z = elu1(az * inv + b4.z);
    hv.w = elu1(aw * inv + b4.w);
    // ---- fused skip + classifier ----
    const float4* xr = (const float4*)(x + n * FIN);
    float4 x0 = xr[0], x1 = xr[1], x2 = xr[2], x3 = xr[3];
    float xk[16] = {x0.x, x0.y, x0.z, x0.w, x1.x, x1.y, x1.z, x1.w,
                    x2.x, x2.y, x2.z, x2.w, x3.x, x3.y, x3.z, x3.w};
    const float4* swT4 = (const float4*)swT;
    const float4* scw4 = (const float4*)scw;
    float4 sk = ((const float4*)skip_b)[lane];
    #pragma unroll
    for (int k = 0; k < FIN; k++) {
        float4 wv = swT4[k * 32 + lane];
        sk.x = fmaf(xk[k], wv.x, sk.x);
        sk.y = fmaf(xk[k], wv.y, sk.y);
        sk.z = fmaf(xk[k], wv.z, sk.z);
        sk.w = fmaf(xk[k], wv.w, sk.w);
    }
    float4 v = make_float4(hv.x + sk.x, hv.y + sk.y, hv.z + sk.z, hv.w + sk.w);
    float p[NCLS];
    #pragma unroll
    for (int c = 0; c < NCLS; c++) {
        float4 cw = scw4[c * 32 + lane];
        p[c] = v.x * cw.x + v.y * cw.y + v.z * cw.z + v.w * cw.w;
        #pragma unroll
        for (int off = 16; off; off >>= 1)
            p[c] += __shfl_xor_sync(0xffffffffu, p[c], off);
    }
    if (lane < NCLS) out[n * NCLS + lane] = p[lane] + cls_b[lane];
}

extern "C" void kernel_launch(void* const* d_in, const int* in_sizes, int n_in,
                              void* d_out, int out_size) {
    const float* x      = (const float*)d_in[0];
    const void*  ei     = d_in[1];
    const float* eattr  = (const float*)d_in[2];
    const float* ee_w1  = (const float*)d_in[3];
    const float* ee_b1  = (const float*)d_in[4];
    const float* ee_w2  = (const float*)d_in[5];
    const float* ee_b2  = (const float*)d_in[6];
    const float* g1_W   = (const float*)d_in[7];
    const float* g1_We  = (const float*)d_in[8];
    const float* g1_as  = (const float*)d_in[9];
    const float* g1_ad  = (const float*)d_in[10];
    const float* g1_ae  = (const float*)d_in[11];
    const float* g1_b   = (const float*)d_in[12];
    const float* g2_W   = (const float*)d_in[13];
    const float* g2_We  = (const float*)d_in[14];
    const float* g2_as  = (const float*)d_in[15];
    const float* g2_ad  = (const float*)d_in[16];
    const float* g2_ae  = (const float*)d_in[17];
    const float* g2_b   = (const float*)d_in[18];
    const float* skip_w = (const float*)d_in[19];
    const float* skip_b = (const float*)d_in[20];
    const float* cls_w  = (const float*)d_in[21];
    const float* cls_b  = (const float*)d_in[22];
    float* out = (float*)d_out;

    static_assert(SMEM_BIG <= 227 * 1024, "smem");
    cudaFuncSetAttribute(k_transform_big, cudaFuncAttributeMaxDynamicSharedMemorySize, SMEM_BIG);

    float *buf1, *buf2, *w1buf, *w2buf;
    cudaGetSymbolAddress((void**)&buf1, g_buf1);
    cudaGetSymbolAddress((void**)&buf2, g_buf2);
    cudaGetSymbolAddress((void**)&w1buf, g_ae1);
    cudaGetSymbolAddress((void**)&w2buf, g_ae2);

    // launches (tsmall 4th: ncu's fixed capture slot; must precede encode
    // because encode consumes layer-1 g_asrc/g_adst)
    k_prep<<<NSB, SCB>>>((const unsigned*)ei);                          // 1
    k_convert_hist<<<NE / 256, 256>>>(ei);                              // 2
    k_scan1<<<NSB, SCB>>>();                                            // 3
    k_transform_small<<<TS_BLOCKS, 256>>>(x, g1_W, g1_as, g1_ad, buf1); // 4
    k_scan23<<<NSB, SCB>>>();                                           // 5
    k_edge_encode<<<NE / 256, 256>>>(eattr, ee_w1, ee_b1, ee_w2, ee_b2,
                                     g1_We, g1_ae, g2_We, g2_ae);       // 6
    // --- layer 1 (weights precomputed in encode) ---
    k_gat<<<(NN * 32 + 255) / 256, 256>>>(buf1, w1buf, g1_b, buf2);     // 7
    // --- layer 2 ---
    k_transform_big<<<(NN + TMB - 1) / TMB, 512, SMEM_BIG>>>(buf2, g2_W, g2_as, g2_ad, buf1); // 8
    k_logit2<<<NE / 256, 256>>>();                                      // 9
    k_gat2_final<<<NN / 8, 256>>>(buf1, w2buf, g2_b,
                                  x, skip_w, skip_b, cls_w, cls_b, out); // 10
}